// round 1
// baseline (speedup 1.0000x reference)
#include <cuda_runtime.h>
#include <math.h>

#define B_SZ 2
#define P_SZ 2048
#define M_SZ 1024
#define H_SZ 16
#define D_SZ 64
#define N3_SZ 3072

// Scratch: __device__ globals (allocation-free rule).
__device__ float g_qkv[(size_t)B_SZ * P_SZ * N3_SZ];   // [B,P,3M] fused qkv
__device__ float g_z  [(size_t)B_SZ * P_SZ * M_SZ];    // [B,P,M]  attention output

// ---------------------------------------------------------------------------
// Generic tiled GEMM: C[rows,N] = A[rows,K] @ W[K,N] + bias, with optional
// 1/sqrt(D) scaling of columns [0, qscale_cols) (the Q slice of the qkv out).
// BM=BN=64, BK=16, 256 threads, 4x4 register micro-tile per thread.
// ---------------------------------------------------------------------------
__global__ __launch_bounds__(256) void gemm_bias_kernel(
    const float* __restrict__ A, const float* __restrict__ W,
    const float* __restrict__ bias, float* __restrict__ C,
    int N, int K, int qscale_cols)
{
    __shared__ float As[16][64];   // transposed A tile: As[k][m]
    __shared__ float Bs[16][64];   // Bs[k][n]

    const int tid = threadIdx.x;
    const int tx  = tid & 15;          // n-groups
    const int ty  = tid >> 4;          // m-groups
    const int row0 = blockIdx.y * 64;
    const int col0 = blockIdx.x * 64;

    float acc[4][4] = {};

    const int ar  = tid >> 2;          // 0..63
    const int akc = (tid & 3) << 2;    // 0,4,8,12
    const int bkr = tid >> 4;          // 0..15
    const int bnc = (tid & 15) << 2;   // 0..60

    const float* Aptr = A + (size_t)(row0 + ar) * K + akc;
    const float* Wptr = W + (size_t)bkr * N + col0 + bnc;

    for (int k0 = 0; k0 < K; k0 += 16) {
        float4 av = *(const float4*)(Aptr + k0);
        As[akc + 0][ar] = av.x;
        As[akc + 1][ar] = av.y;
        As[akc + 2][ar] = av.z;
        As[akc + 3][ar] = av.w;
        *(float4*)&Bs[bkr][bnc] = *(const float4*)(Wptr + (size_t)k0 * N);
        __syncthreads();

        #pragma unroll
        for (int k = 0; k < 16; k++) {
            float4 a4 = *(const float4*)&As[k][ty << 2];
            float4 b4 = *(const float4*)&Bs[k][tx << 2];
            float aa[4] = {a4.x, a4.y, a4.z, a4.w};
            float bb[4] = {b4.x, b4.y, b4.z, b4.w};
            #pragma unroll
            for (int i = 0; i < 4; i++)
                #pragma unroll
                for (int j = 0; j < 4; j++)
                    acc[i][j] = fmaf(aa[i], bb[j], acc[i][j]);
        }
        __syncthreads();
    }

    #pragma unroll
    for (int i = 0; i < 4; i++) {
        const int row = row0 + (ty << 2) + i;
        const int col = col0 + (tx << 2);
        float4 o;
        float* op = &o.x;
        #pragma unroll
        for (int j = 0; j < 4; j++) {
            float v = acc[i][j] + bias[col + j];
            if (col + j < qscale_cols) v *= 0.125f;   // 1/sqrt(64)
            op[j] = v;
        }
        *(float4*)(C + (size_t)row * N + col) = o;
    }
}

// ---------------------------------------------------------------------------
// Flash attention (causal, online softmax), fp32.
// Grid: (P/64 q-tiles, B*H). 256 threads.
// Thread (ty,tx): owns score rows ty*4..ty*4+3 (contiguous) and
// columns tx+16j (strided) -> all smem accesses bank-conflict-free with
// stride-65 padding (bank = row + col + d mod 32, tx distinct across lanes).
// Row softmax stats reduced over the 16-lane tx group via shfl_xor (<16
// never crosses a warp half since lane = (ty&1)*16 + tx).
// ---------------------------------------------------------------------------
__global__ __launch_bounds__(256) void attn_kernel(
    const float* __restrict__ qkv, float* __restrict__ z)
{
    extern __shared__ float sm[];
    float (*Qs)[65] = (float(*)[65])(sm);
    float (*Ks)[65] = (float(*)[65])(sm + 64 * 65);
    float (*Vs)[65] = (float(*)[65])(sm + 2 * 64 * 65);
    float (*Ps)[65] = (float(*)[65])(sm + 3 * 64 * 65);

    const int qt = blockIdx.x;
    const int bh = blockIdx.y;
    const int b  = bh >> 4;
    const int h  = bh & 15;
    const int q0 = qt << 6;

    const int tid = threadIdx.x;
    const int tx  = tid & 15;
    const int ty  = tid >> 4;
    const int row_l = ty << 2;

    const float* qbase = qkv + (size_t)b * P_SZ * N3_SZ + h * D_SZ;      // Q slice
    const float* kbase = qbase + M_SZ;                                   // K slice
    const float* vbase = qbase + 2 * M_SZ;                               // V slice

    // Load Q tile [64 rows x 64 d], coalesced float4, scalar STS (2-way ok).
    {
        const int c = tx << 2;
        #pragma unroll
        for (int pass = 0; pass < 4; pass++) {
            const int r = ty + (pass << 4);
            float4 v = *(const float4*)(qbase + (size_t)(q0 + r) * N3_SZ + c);
            Qs[r][c + 0] = v.x; Qs[r][c + 1] = v.y;
            Qs[r][c + 2] = v.z; Qs[r][c + 3] = v.w;
        }
    }

    float m[4], l[4], acc[4][4];
    #pragma unroll
    for (int i = 0; i < 4; i++) {
        m[i] = -1e30f; l[i] = 0.f;
        #pragma unroll
        for (int j = 0; j < 4; j++) acc[i][j] = 0.f;
    }

    for (int kv = 0; kv <= qt; kv++) {
        const int k0 = kv << 6;
        __syncthreads();   // prev-iter Ps/Vs readers done; Q stores visible (iter 0)

        // Load K/V tiles.
        {
            const int c = tx << 2;
            #pragma unroll
            for (int pass = 0; pass < 4; pass++) {
                const int r = ty + (pass << 4);
                float4 kk = *(const float4*)(kbase + (size_t)(k0 + r) * N3_SZ + c);
                Ks[r][c + 0] = kk.x; Ks[r][c + 1] = kk.y;
                Ks[r][c + 2] = kk.z; Ks[r][c + 3] = kk.w;
                float4 vv = *(const float4*)(vbase + (size_t)(k0 + r) * N3_SZ + c);
                Vs[r][c + 0] = vv.x; Vs[r][c + 1] = vv.y;
                Vs[r][c + 2] = vv.z; Vs[r][c + 3] = vv.w;
            }
        }
        __syncthreads();

        // Scores: s[i][j] = sum_d Q[row_l+i][d] * K[tx+16j][d]
        float s[4][4] = {};
        #pragma unroll 16
        for (int d = 0; d < 64; d++) {
            float a0 = Qs[row_l + 0][d];
            float a1 = Qs[row_l + 1][d];
            float a2 = Qs[row_l + 2][d];
            float a3 = Qs[row_l + 3][d];
            float k0v = Ks[tx +  0][d];
            float k1v = Ks[tx + 16][d];
            float k2v = Ks[tx + 32][d];
            float k3v = Ks[tx + 48][d];
            s[0][0] = fmaf(a0, k0v, s[0][0]); s[0][1] = fmaf(a0, k1v, s[0][1]);
            s[0][2] = fmaf(a0, k2v, s[0][2]); s[0][3] = fmaf(a0, k3v, s[0][3]);
            s[1][0] = fmaf(a1, k0v, s[1][0]); s[1][1] = fmaf(a1, k1v, s[1][1]);
            s[1][2] = fmaf(a1, k2v, s[1][2]); s[1][3] = fmaf(a1, k3v, s[1][3]);
            s[2][0] = fmaf(a2, k0v, s[2][0]); s[2][1] = fmaf(a2, k1v, s[2][1]);
            s[2][2] = fmaf(a2, k2v, s[2][2]); s[2][3] = fmaf(a2, k3v, s[2][3]);
            s[3][0] = fmaf(a3, k0v, s[3][0]); s[3][1] = fmaf(a3, k1v, s[3][1]);
            s[3][2] = fmaf(a3, k2v, s[3][2]); s[3][3] = fmaf(a3, k3v, s[3][3]);
        }

        const bool diag = (kv == qt);

        // Online softmax per owned row.
        #pragma unroll
        for (int i = 0; i < 4; i++) {
            const int rg = q0 + row_l + i;
            if (diag) {
                #pragma unroll
                for (int j = 0; j < 4; j++)
                    if (k0 + tx + (j << 4) > rg) s[i][j] = -1e30f;
            }
            float mx = fmaxf(fmaxf(s[i][0], s[i][1]), fmaxf(s[i][2], s[i][3]));
            #pragma unroll
            for (int o = 1; o < 16; o <<= 1)
                mx = fmaxf(mx, __shfl_xor_sync(0xffffffffu, mx, o));
            const float mnew  = fmaxf(m[i], mx);
            const float alpha = __expf(m[i] - mnew);
            float rs = 0.f;
            #pragma unroll
            for (int j = 0; j < 4; j++) {
                s[i][j] = __expf(s[i][j] - mnew);
                rs += s[i][j];
            }
            #pragma unroll
            for (int o = 1; o < 16; o <<= 1)
                rs += __shfl_xor_sync(0xffffffffu, rs, o);
            l[i] = l[i] * alpha + rs;
            m[i] = mnew;
            #pragma unroll
            for (int j = 0; j < 4; j++) acc[i][j] *= alpha;
        }

        // Stage P through smem for the PV micro-kernel.
        #pragma unroll
        for (int i = 0; i < 4; i++)
            #pragma unroll
            for (int j = 0; j < 4; j++)
                Ps[row_l + i][tx + (j << 4)] = s[i][j];
        __syncthreads();

        // PV: acc[i][j] += sum_c P[row_l+i][c] * V[c][tx+16j]
        #pragma unroll 16
        for (int c = 0; c < 64; c++) {
            float p0 = Ps[row_l + 0][c];
            float p1 = Ps[row_l + 1][c];
            float p2 = Ps[row_l + 2][c];
            float p3 = Ps[row_l + 3][c];
            float v0 = Vs[c][tx +  0];
            float v1 = Vs[c][tx + 16];
            float v2 = Vs[c][tx + 32];
            float v3 = Vs[c][tx + 48];
            acc[0][0] = fmaf(p0, v0, acc[0][0]); acc[0][1] = fmaf(p0, v1, acc[0][1]);
            acc[0][2] = fmaf(p0, v2, acc[0][2]); acc[0][3] = fmaf(p0, v3, acc[0][3]);
            acc[1][0] = fmaf(p1, v0, acc[1][0]); acc[1][1] = fmaf(p1, v1, acc[1][1]);
            acc[1][2] = fmaf(p1, v2, acc[1][2]); acc[1][3] = fmaf(p1, v3, acc[1][3]);
            acc[2][0] = fmaf(p2, v0, acc[2][0]); acc[2][1] = fmaf(p2, v1, acc[2][1]);
            acc[2][2] = fmaf(p2, v2, acc[2][2]); acc[2][3] = fmaf(p2, v3, acc[2][3]);
            acc[3][0] = fmaf(p3, v0, acc[3][0]); acc[3][1] = fmaf(p3, v1, acc[3][1]);
            acc[3][2] = fmaf(p3, v2, acc[3][2]); acc[3][3] = fmaf(p3, v3, acc[3][3]);
        }
    }

    // Epilogue: z[b][q0+row][h*64 + col] = acc / l
    #pragma unroll
    for (int i = 0; i < 4; i++) {
        const float inv = 1.f / l[i];
        const size_t rbase = ((size_t)b * P_SZ + q0 + row_l + i) * M_SZ + h * D_SZ;
        #pragma unroll
        for (int j = 0; j < 4; j++)
            z[rbase + tx + (j << 4)] = acc[i][j] * inv;
    }
}

// ---------------------------------------------------------------------------
extern "C" void kernel_launch(void* const* d_in, const int* in_sizes, int n_in,
                              void* d_out, int out_size)
{
    (void)in_sizes; (void)n_in; (void)out_size;
    const float* x      = (const float*)d_in[0];
    const float* W_attn = (const float*)d_in[1];
    const float* b_attn = (const float*)d_in[2];
    const float* W_proj = (const float*)d_in[3];
    const float* b_proj = (const float*)d_in[4];
    float* out = (float*)d_out;

    float *qkv = nullptr, *zbuf = nullptr;
    cudaGetSymbolAddress((void**)&qkv,  g_qkv);
    cudaGetSymbolAddress((void**)&zbuf, g_z);

    // 1) Fused QKV projection (+bias, Q pre-scaled by 1/sqrt(D)).
    dim3 g1(N3_SZ / 64, (B_SZ * P_SZ) / 64);
    gemm_bias_kernel<<<g1, 256>>>(x, W_attn, b_attn, qkv, N3_SZ, M_SZ, M_SZ);

    // 2) Causal flash attention.
    const int smem_bytes = 4 * 64 * 65 * (int)sizeof(float);   // 66560 B
    cudaFuncSetAttribute(attn_kernel,
                         cudaFuncAttributeMaxDynamicSharedMemorySize, smem_bytes);
    attn_kernel<<<dim3(P_SZ / 64, B_SZ * H_SZ), 256, smem_bytes>>>(qkv, zbuf);

    // 3) Output projection.
    dim3 g2(M_SZ / 64, (B_SZ * P_SZ) / 64);
    gemm_bias_kernel<<<g2, 256>>>(zbuf, W_proj, b_proj, out, M_SZ, M_SZ, 0);
}

// round 3
// speedup vs baseline: 1.5927x; 1.5927x over previous
#include <cuda_runtime.h>
#include <cuda_bf16.h>
#include <cstdint>
#include <math.h>

#define B_SZ 2
#define P_SZ 2048
#define M_SZ 1024
#define H_SZ 16
#define D_SZ 64
#define N3_SZ 3072
#define R_SZ (B_SZ * P_SZ)      // 4096 rows
#define K_SZ M_SZ               // 1024 reduction dim (both GEMMs)

// ---------------- scratch (__device__ globals; allocation-free rule) -------
__device__ float g_qkv[(size_t)R_SZ * N3_SZ];
__device__ float g_z  [(size_t)R_SZ * M_SZ];
__device__ __nv_bfloat16 g_xhi[(size_t)R_SZ * K_SZ];
__device__ __nv_bfloat16 g_xlo[(size_t)R_SZ * K_SZ];
__device__ __nv_bfloat16 g_wah[(size_t)N3_SZ * K_SZ];   // W_attn^T split
__device__ __nv_bfloat16 g_wal[(size_t)N3_SZ * K_SZ];
__device__ __nv_bfloat16 g_wph[(size_t)M_SZ * K_SZ];    // W_proj^T split
__device__ __nv_bfloat16 g_wpl[(size_t)M_SZ * K_SZ];
__device__ __nv_bfloat16 g_zhi[(size_t)R_SZ * K_SZ];
__device__ __nv_bfloat16 g_zlo[(size_t)R_SZ * K_SZ];

// ---------------- PTX helpers (base ISA only; no tcgen05) ------------------
__device__ __forceinline__ uint32_t smem_u32(const void* p) {
    uint32_t a;
    asm("{ .reg .u64 t; cvta.to.shared.u64 t, %1; cvt.u32.u64 %0, t; }" : "=r"(a) : "l"(p));
    return a;
}
__device__ __forceinline__ void ldsm4(uint32_t* r, uint32_t addr) {
    asm volatile("ldmatrix.sync.aligned.m8n8.x4.shared.b16 {%0,%1,%2,%3}, [%4];"
                 : "=r"(r[0]), "=r"(r[1]), "=r"(r[2]), "=r"(r[3]) : "r"(addr));
}
__device__ __forceinline__ void ldsm2(uint32_t* r, uint32_t addr) {
    asm volatile("ldmatrix.sync.aligned.m8n8.x2.shared.b16 {%0,%1}, [%2];"
                 : "=r"(r[0]), "=r"(r[1]) : "r"(addr));
}
__device__ __forceinline__ void mma16816(float* c, const uint32_t* a, const uint32_t* b) {
    asm volatile(
        "mma.sync.aligned.m16n8k16.row.col.f32.bf16.bf16.f32 "
        "{%0,%1,%2,%3}, {%4,%5,%6,%7}, {%8,%9}, {%0,%1,%2,%3};"
        : "+f"(c[0]), "+f"(c[1]), "+f"(c[2]), "+f"(c[3])
        : "r"(a[0]), "r"(a[1]), "r"(a[2]), "r"(a[3]), "r"(b[0]), "r"(b[1]));
}
__device__ __forceinline__ void cpasync16(uint32_t saddr, const void* gaddr) {
    asm volatile("cp.async.cg.shared.global [%0], [%1], 16;" :: "r"(saddr), "l"(gaddr) : "memory");
}

// ---------------- fp32 -> bf16 hi/lo split (row-major copy) ----------------
struct alignas(8) bf16x4 { __nv_bfloat162 a, b; };

__global__ __launch_bounds__(256) void split_kernel(
    const float* __restrict__ in, __nv_bfloat16* __restrict__ hi,
    __nv_bfloat16* __restrict__ lo, int n4)
{
    int i = blockIdx.x * 256 + threadIdx.x;
    if (i >= n4) return;
    float4 v = ((const float4*)in)[i];
    float h0 = __bfloat162float(__float2bfloat16(v.x));
    float h1 = __bfloat162float(__float2bfloat16(v.y));
    float h2 = __bfloat162float(__float2bfloat16(v.z));
    float h3 = __bfloat162float(__float2bfloat16(v.w));
    bf16x4 H, L;
    H.a = __floats2bfloat162_rn(h0, h1);
    H.b = __floats2bfloat162_rn(h2, h3);
    L.a = __floats2bfloat162_rn(v.x - h0, v.y - h1);
    L.b = __floats2bfloat162_rn(v.z - h2, v.w - h3);
    ((bf16x4*)hi)[i] = H;
    ((bf16x4*)lo)[i] = L;
}

// ------------- W [K,N] fp32 -> Wt [N,K] bf16 hi/lo (transpose + split) -----
__global__ __launch_bounds__(256) void tsplit_kernel(
    const float* __restrict__ W, __nv_bfloat16* __restrict__ hi,
    __nv_bfloat16* __restrict__ lo, int K, int N)
{
    __shared__ float s[32][33];
    const int n0 = blockIdx.x * 32, k0 = blockIdx.y * 32;
    const int tx = threadIdx.x & 31, ty = threadIdx.x >> 5;   // 32 x 8
    #pragma unroll
    for (int i = 0; i < 4; i++)
        s[ty + 8 * i][tx] = W[(size_t)(k0 + ty + 8 * i) * N + n0 + tx];
    __syncthreads();
    #pragma unroll
    for (int i = 0; i < 4; i++) {
        int r = ty + 8 * i;                 // local n
        float v = s[tx][r];                 // W[k0+tx][n0+r]
        float h = __bfloat162float(__float2bfloat16(v));
        size_t o = (size_t)(n0 + r) * K + k0 + tx;
        hi[o] = __float2bfloat16(h);
        lo[o] = __float2bfloat16(v - h);
    }
}

// ---------------- split-bf16 mma.sync GEMM ---------------------------------
// C[row0:+128, col0:+128] = A[.,1024] @ Wt[.,1024]^T (+bias, optional qscale)
// BM=BN=128, BK=32. 8 warps: wm in {0,1} (64 rows), wn in {0..3} (32 cols).
// smem tiles padded: row stride 40 halfs (80B) -> ldmatrix conflict-free.
#define GK_CH   (K_SZ / 32)          // 32 chunks
#define GT_TILE 10240                // 128 rows * 80 B
#define GT_STG  (4 * GT_TILE)        // Ah, Al, Bh, Bl
#define GT_SMEM (2 * GT_STG)         // 81920 B, double buffered

__global__ __launch_bounds__(256) void gemm_mma_kernel(
    const __nv_bfloat16* __restrict__ Ah, const __nv_bfloat16* __restrict__ Al,
    const __nv_bfloat16* __restrict__ Bh, const __nv_bfloat16* __restrict__ Bl,
    const float* __restrict__ bias, float* __restrict__ C,
    int N, int qscale_cols)
{
    extern __shared__ char smraw[];
    const uint32_t sbase = smem_u32(smraw);

    const int tid = threadIdx.x;
    const int wid = tid >> 5, lane = tid & 31;
    const int wm = wid & 1, wn = wid >> 1;
    const int g = lane >> 2, t = lane & 3;
    const int row0 = blockIdx.y << 7;
    const int col0 = blockIdx.x << 7;

    const __nv_bfloat16* srcs[4] = {Ah, Al, Bh, Bl};

    // per-thread cp.async mapping: 2 phases x (row = g>>2, q = g&3)
    const int ldr0 = tid >> 2, ldq = tid & 3;          // phase 0
    const int ldr1 = (256 + tid) >> 2;                  // phase 1 row

    auto load_chunk = [&](int c, int s) {
        const int k0 = c << 5;
        const uint32_t stg = sbase + (uint32_t)s * GT_STG;
        #pragma unroll
        for (int arr = 0; arr < 4; arr++) {
            const __nv_bfloat16* src = srcs[arr];
            const int rbase = (arr < 2) ? row0 : col0;
            const uint32_t tb = stg + (uint32_t)arr * GT_TILE;
            cpasync16(tb + (uint32_t)(ldr0 * 80 + ldq * 16),
                      src + (size_t)(rbase + ldr0) * K_SZ + k0 + ldq * 8);
            cpasync16(tb + (uint32_t)(ldr1 * 80 + ldq * 16),
                      src + (size_t)(rbase + ldr1) * K_SZ + k0 + ldq * 8);
        }
    };

    float acc[4][4][4] = {};

    // ldmatrix lane addressing (byte offsets inside a tile)
    const int a_row = lane & 15;                    // rows 0..15
    const int a_cb  = (lane >> 4) << 4;             // 0 or 16 bytes
    const int b_row = lane & 7;                     // rows 0..7 (x2: lanes 0..15)
    const int b_cb  = ((lane >> 3) & 1) << 4;       // 0 or 16 bytes

    load_chunk(0, 0);
    asm volatile("cp.async.commit_group;" ::: "memory");

    for (int c = 0; c < GK_CH; c++) {
        const int s = c & 1;
        if (c + 1 < GK_CH) {
            load_chunk(c + 1, s ^ 1);
            asm volatile("cp.async.commit_group;" ::: "memory");
            asm volatile("cp.async.wait_group 1;" ::: "memory");
        } else {
            asm volatile("cp.async.wait_group 0;" ::: "memory");
        }
        __syncthreads();

        const uint32_t stg = sbase + (uint32_t)s * GT_STG;
        const uint32_t tAh = stg;
        const uint32_t tAl = stg + GT_TILE;
        const uint32_t tBh = stg + 2 * GT_TILE;
        const uint32_t tBl = stg + 3 * GT_TILE;

        #pragma unroll
        for (int ks = 0; ks < 2; ks++) {
            const int kb = ks << 5;                 // 32B per k16 step
            uint32_t ah[4][4], al[4][4], bh[4][2], bl[4][2];
            #pragma unroll
            for (int mt = 0; mt < 4; mt++) {
                const uint32_t ro = (uint32_t)((wm * 64 + mt * 16 + a_row) * 80 + kb + a_cb);
                ldsm4(ah[mt], tAh + ro);
                ldsm4(al[mt], tAl + ro);
            }
            #pragma unroll
            for (int nt = 0; nt < 4; nt++) {
                const uint32_t ro = (uint32_t)((wn * 32 + nt * 8 + b_row) * 80 + kb + b_cb);
                ldsm2(bh[nt], tBh + ro);
                ldsm2(bl[nt], tBl + ro);
            }
            #pragma unroll
            for (int mt = 0; mt < 4; mt++)
                #pragma unroll
                for (int nt = 0; nt < 4; nt++) {
                    mma16816(acc[mt][nt], ah[mt], bh[nt]);
                    mma16816(acc[mt][nt], ah[mt], bl[nt]);
                    mma16816(acc[mt][nt], al[mt], bh[nt]);
                }
        }
        __syncthreads();
    }

    // Epilogue: bias + optional q-scale, float2 stores.
    #pragma unroll
    for (int mt = 0; mt < 4; mt++) {
        const int ra = row0 + wm * 64 + mt * 16 + g;
        const int rb = ra + 8;
        #pragma unroll
        for (int nt = 0; nt < 4; nt++) {
            const int col = col0 + wn * 32 + nt * 8 + 2 * t;
            const float b0 = bias[col], b1 = bias[col + 1];
            float v0 = acc[mt][nt][0] + b0, v1 = acc[mt][nt][1] + b1;
            float v2 = acc[mt][nt][2] + b0, v3 = acc[mt][nt][3] + b1;
            if (col < qscale_cols)     { v0 *= 0.125f; v2 *= 0.125f; }
            if (col + 1 < qscale_cols) { v1 *= 0.125f; v3 *= 0.125f; }
            *(float2*)(C + (size_t)ra * N + col) = make_float2(v0, v1);
            *(float2*)(C + (size_t)rb * N + col) = make_float2(v2, v3);
        }
    }
}

// ---------------- flash attention (SIMT fp32, unchanged) -------------------
__global__ __launch_bounds__(256) void attn_kernel(
    const float* __restrict__ qkv, float* __restrict__ z)
{
    extern __shared__ float sm[];
    float (*Qs)[65] = (float(*)[65])(sm);
    float (*Ks)[65] = (float(*)[65])(sm + 64 * 65);
    float (*Vs)[65] = (float(*)[65])(sm + 2 * 64 * 65);
    float (*Ps)[65] = (float(*)[65])(sm + 3 * 64 * 65);

    const int qt = blockIdx.x;
    const int bh = blockIdx.y;
    const int b  = bh >> 4;
    const int h  = bh & 15;
    const int q0 = qt << 6;

    const int tid = threadIdx.x;
    const int tx  = tid & 15;
    const int ty  = tid >> 4;
    const int row_l = ty << 2;

    const float* qbase = qkv + (size_t)b * P_SZ * N3_SZ + h * D_SZ;
    const float* kbase = qbase + M_SZ;
    const float* vbase = qbase + 2 * M_SZ;

    {
        const int c = tx << 2;
        #pragma unroll
        for (int pass = 0; pass < 4; pass++) {
            const int r = ty + (pass << 4);
            float4 v = *(const float4*)(qbase + (size_t)(q0 + r) * N3_SZ + c);
            Qs[r][c + 0] = v.x; Qs[r][c + 1] = v.y;
            Qs[r][c + 2] = v.z; Qs[r][c + 3] = v.w;
        }
    }

    float m[4], l[4], acc[4][4];
    #pragma unroll
    for (int i = 0; i < 4; i++) {
        m[i] = -1e30f; l[i] = 0.f;
        #pragma unroll
        for (int j = 0; j < 4; j++) acc[i][j] = 0.f;
    }

    for (int kv = 0; kv <= qt; kv++) {
        const int k0 = kv << 6;
        __syncthreads();
        {
            const int c = tx << 2;
            #pragma unroll
            for (int pass = 0; pass < 4; pass++) {
                const int r = ty + (pass << 4);
                float4 kk = *(const float4*)(kbase + (size_t)(k0 + r) * N3_SZ + c);
                Ks[r][c + 0] = kk.x; Ks[r][c + 1] = kk.y;
                Ks[r][c + 2] = kk.z; Ks[r][c + 3] = kk.w;
                float4 vv = *(const float4*)(vbase + (size_t)(k0 + r) * N3_SZ + c);
                Vs[r][c + 0] = vv.x; Vs[r][c + 1] = vv.y;
                Vs[r][c + 2] = vv.z; Vs[r][c + 3] = vv.w;
            }
        }
        __syncthreads();

        float s[4][4] = {};
        #pragma unroll 16
        for (int d = 0; d < 64; d++) {
            float a0 = Qs[row_l + 0][d];
            float a1 = Qs[row_l + 1][d];
            float a2 = Qs[row_l + 2][d];
            float a3 = Qs[row_l + 3][d];
            float k0v = Ks[tx +  0][d];
            float k1v = Ks[tx + 16][d];
            float k2v = Ks[tx + 32][d];
            float k3v = Ks[tx + 48][d];
            s[0][0] = fmaf(a0, k0v, s[0][0]); s[0][1] = fmaf(a0, k1v, s[0][1]);
            s[0][2] = fmaf(a0, k2v, s[0][2]); s[0][3] = fmaf(a0, k3v, s[0][3]);
            s[1][0] = fmaf(a1, k0v, s[1][0]); s[1][1] = fmaf(a1, k1v, s[1][1]);
            s[1][2] = fmaf(a1, k2v, s[1][2]); s[1][3] = fmaf(a1, k3v, s[1][3]);
            s[2][0] = fmaf(a2, k0v, s[2][0]); s[2][1] = fmaf(a2, k1v, s[2][1]);
            s[2][2] = fmaf(a2, k2v, s[2][2]); s[2][3] = fmaf(a2, k3v, s[2][3]);
            s[3][0] = fmaf(a3, k0v, s[3][0]); s[3][1] = fmaf(a3, k1v, s[3][1]);
            s[3][2] = fmaf(a3, k2v, s[3][2]); s[3][3] = fmaf(a3, k3v, s[3][3]);
        }

        const bool diag = (kv == qt);
        #pragma unroll
        for (int i = 0; i < 4; i++) {
            const int rg = q0 + row_l + i;
            if (diag) {
                #pragma unroll
                for (int j = 0; j < 4; j++)
                    if (k0 + tx + (j << 4) > rg) s[i][j] = -1e30f;
            }
            float mx = fmaxf(fmaxf(s[i][0], s[i][1]), fmaxf(s[i][2], s[i][3]));
            #pragma unroll
            for (int o = 1; o < 16; o <<= 1)
                mx = fmaxf(mx, __shfl_xor_sync(0xffffffffu, mx, o));
            const float mnew  = fmaxf(m[i], mx);
            const float alpha = __expf(m[i] - mnew);
            float rs = 0.f;
            #pragma unroll
            for (int j = 0; j < 4; j++) {
                s[i][j] = __expf(s[i][j] - mnew);
                rs += s[i][j];
            }
            #pragma unroll
            for (int o = 1; o < 16; o <<= 1)
                rs += __shfl_xor_sync(0xffffffffu, rs, o);
            l[i] = l[i] * alpha + rs;
            m[i] = mnew;
            #pragma unroll
            for (int j = 0; j < 4; j++) acc[i][j] *= alpha;
        }

        #pragma unroll
        for (int i = 0; i < 4; i++)
            #pragma unroll
            for (int j = 0; j < 4; j++)
                Ps[row_l + i][tx + (j << 4)] = s[i][j];
        __syncthreads();

        #pragma unroll 16
        for (int c = 0; c < 64; c++) {
            float p0 = Ps[row_l + 0][c];
            float p1 = Ps[row_l + 1][c];
            float p2 = Ps[row_l + 2][c];
            float p3 = Ps[row_l + 3][c];
            float v0 = Vs[c][tx +  0];
            float v1 = Vs[c][tx + 16];
            float v2 = Vs[c][tx + 32];
            float v3 = Vs[c][tx + 48];
            acc[0][0] = fmaf(p0, v0, acc[0][0]); acc[0][1] = fmaf(p0, v1, acc[0][1]);
            acc[0][2] = fmaf(p0, v2, acc[0][2]); acc[0][3] = fmaf(p0, v3, acc[0][3]);
            acc[1][0] = fmaf(p1, v0, acc[1][0]); acc[1][1] = fmaf(p1, v1, acc[1][1]);
            acc[1][2] = fmaf(p1, v2, acc[1][2]); acc[1][3] = fmaf(p1, v3, acc[1][3]);
            acc[2][0] = fmaf(p2, v0, acc[2][0]); acc[2][1] = fmaf(p2, v1, acc[2][1]);
            acc[2][2] = fmaf(p2, v2, acc[2][2]); acc[2][3] = fmaf(p2, v3, acc[2][3]);
            acc[3][0] = fmaf(p3, v0, acc[3][0]); acc[3][1] = fmaf(p3, v1, acc[3][1]);
            acc[3][2] = fmaf(p3, v2, acc[3][2]); acc[3][3] = fmaf(p3, v3, acc[3][3]);
        }
    }

    #pragma unroll
    for (int i = 0; i < 4; i++) {
        const float inv = 1.f / l[i];
        const size_t rbase = ((size_t)b * P_SZ + q0 + row_l + i) * M_SZ + h * D_SZ;
        #pragma unroll
        for (int j = 0; j < 4; j++)
            z[rbase + tx + (j << 4)] = acc[i][j] * inv;
    }
}

// ---------------------------------------------------------------------------
extern "C" void kernel_launch(void* const* d_in, const int* in_sizes, int n_in,
                              void* d_out, int out_size)
{
    (void)in_sizes; (void)n_in; (void)out_size;
    const float* x      = (const float*)d_in[0];
    const float* W_attn = (const float*)d_in[1];
    const float* b_attn = (const float*)d_in[2];
    const float* W_proj = (const float*)d_in[3];
    const float* b_proj = (const float*)d_in[4];
    float* out = (float*)d_out;

    float *qkv, *zbuf;
    __nv_bfloat16 *xhi, *xlo, *wah, *wal, *wph, *wpl, *zhi, *zlo;
    cudaGetSymbolAddress((void**)&qkv,  g_qkv);
    cudaGetSymbolAddress((void**)&zbuf, g_z);
    cudaGetSymbolAddress((void**)&xhi,  g_xhi);
    cudaGetSymbolAddress((void**)&xlo,  g_xlo);
    cudaGetSymbolAddress((void**)&wah,  g_wah);
    cudaGetSymbolAddress((void**)&wal,  g_wal);
    cudaGetSymbolAddress((void**)&wph,  g_wph);
    cudaGetSymbolAddress((void**)&wpl,  g_wpl);
    cudaGetSymbolAddress((void**)&zhi,  g_zhi);
    cudaGetSymbolAddress((void**)&zlo,  g_zlo);

    cudaFuncSetAttribute(gemm_mma_kernel,
                         cudaFuncAttributeMaxDynamicSharedMemorySize, GT_SMEM);
    cudaFuncSetAttribute(attn_kernel,
                         cudaFuncAttributeMaxDynamicSharedMemorySize,
                         4 * 64 * 65 * (int)sizeof(float));

    // 0) conversions
    split_kernel<<<(R_SZ * K_SZ / 4 + 255) / 256, 256>>>(x, xhi, xlo, R_SZ * K_SZ / 4);
    tsplit_kernel<<<dim3(N3_SZ / 32, K_SZ / 32), 256>>>(W_attn, wah, wal, K_SZ, N3_SZ);
    tsplit_kernel<<<dim3(M_SZ / 32, K_SZ / 32), 256>>>(W_proj, wph, wpl, K_SZ, M_SZ);

    // 1) QKV projection (bias + q-scale fused)
    gemm_mma_kernel<<<dim3(N3_SZ / 128, R_SZ / 128), 256, GT_SMEM>>>(
        xhi, xlo, wah, wal, b_attn, qkv, N3_SZ, M_SZ);

    // 2) causal flash attention
    const int smem_attn = 4 * 64 * 65 * (int)sizeof(float);
    attn_kernel<<<dim3(P_SZ / 64, B_SZ * H_SZ), 256, smem_attn>>>(qkv, zbuf);

    // 3) split z, output projection
    split_kernel<<<(R_SZ * K_SZ / 4 + 255) / 256, 256>>>(zbuf, zhi, zlo, R_SZ * K_SZ / 4);
    gemm_mma_kernel<<<dim3(M_SZ / 128, R_SZ / 128), 256, GT_SMEM>>>(
        zhi, zlo, wph, wpl, b_proj, out, M_SZ, 0);
}

// round 4
// speedup vs baseline: 1.8029x; 1.1320x over previous
#include <cuda_runtime.h>
#include <cuda_bf16.h>
#include <cstdint>
#include <string.h>
#include <math.h>

#define B_SZ 2
#define P_SZ 2048
#define M_SZ 1024
#define H_SZ 16
#define D_SZ 64
#define N3_SZ 3072
#define R_SZ (B_SZ * P_SZ)      // 4096
#define K_SZ M_SZ               // 1024
#define BH_SZ (B_SZ * H_SZ)     // 32

// ---------------- scratch (__device__ globals) -----------------------------
__device__ __nv_bfloat16 g_xhi[(size_t)R_SZ * K_SZ];
__device__ __nv_bfloat16 g_xlo[(size_t)R_SZ * K_SZ];
__device__ __nv_bfloat16 g_wah[(size_t)N3_SZ * K_SZ];
__device__ __nv_bfloat16 g_wal[(size_t)N3_SZ * K_SZ];
__device__ __nv_bfloat16 g_wph[(size_t)M_SZ * K_SZ];
__device__ __nv_bfloat16 g_wpl[(size_t)M_SZ * K_SZ];
__device__ __nv_bfloat16 g_qh[(size_t)BH_SZ * P_SZ * D_SZ];
__device__ __nv_bfloat16 g_ql[(size_t)BH_SZ * P_SZ * D_SZ];
__device__ __nv_bfloat16 g_kh[(size_t)BH_SZ * P_SZ * D_SZ];
__device__ __nv_bfloat16 g_kl[(size_t)BH_SZ * P_SZ * D_SZ];
__device__ __nv_bfloat16 g_vh[(size_t)BH_SZ * P_SZ * D_SZ];
__device__ __nv_bfloat16 g_vl[(size_t)BH_SZ * P_SZ * D_SZ];
__device__ __nv_bfloat16 g_zh[(size_t)R_SZ * K_SZ];
__device__ __nv_bfloat16 g_zl[(size_t)R_SZ * K_SZ];

// ---------------- PTX helpers (base ISA) -----------------------------------
__device__ __forceinline__ uint32_t smem_u32(const void* p) {
    uint32_t a;
    asm("{ .reg .u64 t; cvta.to.shared.u64 t, %1; cvt.u32.u64 %0, t; }" : "=r"(a) : "l"(p));
    return a;
}
__device__ __forceinline__ void ldsm4(uint32_t* r, uint32_t addr) {
    asm volatile("ldmatrix.sync.aligned.m8n8.x4.shared.b16 {%0,%1,%2,%3}, [%4];"
                 : "=r"(r[0]), "=r"(r[1]), "=r"(r[2]), "=r"(r[3]) : "r"(addr));
}
__device__ __forceinline__ void ldsm4t(uint32_t* r, uint32_t addr) {
    asm volatile("ldmatrix.sync.aligned.m8n8.x4.trans.shared.b16 {%0,%1,%2,%3}, [%4];"
                 : "=r"(r[0]), "=r"(r[1]), "=r"(r[2]), "=r"(r[3]) : "r"(addr));
}
__device__ __forceinline__ void ldsm2(uint32_t* r, uint32_t addr) {
    asm volatile("ldmatrix.sync.aligned.m8n8.x2.shared.b16 {%0,%1}, [%2];"
                 : "=r"(r[0]), "=r"(r[1]) : "r"(addr));
}
__device__ __forceinline__ void mma16816(float* c, const uint32_t* a, const uint32_t* b) {
    asm volatile(
        "mma.sync.aligned.m16n8k16.row.col.f32.bf16.bf16.f32 "
        "{%0,%1,%2,%3}, {%4,%5,%6,%7}, {%8,%9}, {%0,%1,%2,%3};"
        : "+f"(c[0]), "+f"(c[1]), "+f"(c[2]), "+f"(c[3])
        : "r"(a[0]), "r"(a[1]), "r"(a[2]), "r"(a[3]), "r"(b[0]), "r"(b[1]));
}
__device__ __forceinline__ void cpasync16(uint32_t saddr, const void* gaddr) {
    asm volatile("cp.async.cg.shared.global [%0], [%1], 16;" :: "r"(saddr), "l"(gaddr) : "memory");
}
// split two fp32 into packed bf16x2 hi + bf16x2 lo residual
__device__ __forceinline__ void split2(float a, float b, uint32_t& hu, uint32_t& lu) {
    __nv_bfloat16 ha = __float2bfloat16(a), hb = __float2bfloat16(b);
    float ra = a - __bfloat162float(ha), rb = b - __bfloat162float(hb);
    __nv_bfloat162 H = __halves2bfloat162(ha, hb);
    __nv_bfloat162 L = __floats2bfloat162_rn(ra, rb);
    memcpy(&hu, &H, 4); memcpy(&lu, &L, 4);
}

// ---------------- fp32 -> bf16 hi/lo split ---------------------------------
struct alignas(8) bf16x4 { __nv_bfloat162 a, b; };

__global__ __launch_bounds__(256) void split_kernel(
    const float* __restrict__ in, __nv_bfloat16* __restrict__ hi,
    __nv_bfloat16* __restrict__ lo, int n4)
{
    int i = blockIdx.x * 256 + threadIdx.x;
    if (i >= n4) return;
    float4 v = ((const float4*)in)[i];
    float h0 = __bfloat162float(__float2bfloat16(v.x));
    float h1 = __bfloat162float(__float2bfloat16(v.y));
    float h2 = __bfloat162float(__float2bfloat16(v.z));
    float h3 = __bfloat162float(__float2bfloat16(v.w));
    bf16x4 H, L;
    H.a = __floats2bfloat162_rn(h0, h1);
    H.b = __floats2bfloat162_rn(h2, h3);
    L.a = __floats2bfloat162_rn(v.x - h0, v.y - h1);
    L.b = __floats2bfloat162_rn(v.z - h2, v.w - h3);
    ((bf16x4*)hi)[i] = H;
    ((bf16x4*)lo)[i] = L;
}

// ------------- W [K,N] fp32 -> Wt [N,K] bf16 hi/lo -------------------------
__global__ __launch_bounds__(256) void tsplit_kernel(
    const float* __restrict__ W, __nv_bfloat16* __restrict__ hi,
    __nv_bfloat16* __restrict__ lo, int K, int N)
{
    __shared__ float s[32][33];
    const int n0 = blockIdx.x * 32, k0 = blockIdx.y * 32;
    const int tx = threadIdx.x & 31, ty = threadIdx.x >> 5;
    #pragma unroll
    for (int i = 0; i < 4; i++)
        s[ty + 8 * i][tx] = W[(size_t)(k0 + ty + 8 * i) * N + n0 + tx];
    __syncthreads();
    #pragma unroll
    for (int i = 0; i < 4; i++) {
        int r = ty + 8 * i;
        float v = s[tx][r];
        float h = __bfloat162float(__float2bfloat16(v));
        size_t o = (size_t)(n0 + r) * K + k0 + tx;
        hi[o] = __float2bfloat16(h);
        lo[o] = __float2bfloat16(v - h);
    }
}

// ---------------- split-bf16 mma GEMM --------------------------------------
// MODE 0: C fp32 = A@Wt^T + bias (proj -> d_out)
// MODE 1: epilogue splits qkv to bf16 hi/lo per-head buffers (+0.125 q scale)
#define GK_CH   (K_SZ / 32)
#define GT_TILE 10240
#define GT_STG  (4 * GT_TILE)
#define GT_SMEM (2 * GT_STG)

template<int MODE>
__global__ __launch_bounds__(256, 2) void gemm_mma_kernel(
    const __nv_bfloat16* __restrict__ Ah, const __nv_bfloat16* __restrict__ Al,
    const __nv_bfloat16* __restrict__ Bh, const __nv_bfloat16* __restrict__ Bl,
    const float* __restrict__ bias, float* __restrict__ C, int N,
    __nv_bfloat16* __restrict__ qh, __nv_bfloat16* __restrict__ ql,
    __nv_bfloat16* __restrict__ kh, __nv_bfloat16* __restrict__ kl,
    __nv_bfloat16* __restrict__ vh, __nv_bfloat16* __restrict__ vl)
{
    extern __shared__ char smraw[];
    const uint32_t sbase = smem_u32(smraw);

    const int tid = threadIdx.x;
    const int wid = tid >> 5, lane = tid & 31;
    const int wm = wid & 1, wn = wid >> 1;
    const int g = lane >> 2, t = lane & 3;
    const int row0 = blockIdx.y << 7;
    const int col0 = blockIdx.x << 7;

    const __nv_bfloat16* srcs[4] = {Ah, Al, Bh, Bl};
    const int ldr0 = tid >> 2, ldq = tid & 3;
    const int ldr1 = (256 + tid) >> 2;

    auto load_chunk = [&](int c, int s) {
        const int k0 = c << 5;
        const uint32_t stg = sbase + (uint32_t)s * GT_STG;
        #pragma unroll
        for (int arr = 0; arr < 4; arr++) {
            const __nv_bfloat16* src = srcs[arr];
            const int rbase = (arr < 2) ? row0 : col0;
            const uint32_t tb = stg + (uint32_t)arr * GT_TILE;
            cpasync16(tb + (uint32_t)(ldr0 * 80 + ldq * 16),
                      src + (size_t)(rbase + ldr0) * K_SZ + k0 + ldq * 8);
            cpasync16(tb + (uint32_t)(ldr1 * 80 + ldq * 16),
                      src + (size_t)(rbase + ldr1) * K_SZ + k0 + ldq * 8);
        }
    };

    float acc[4][4][4] = {};
    const int a_row = lane & 15;
    const int a_cb  = (lane >> 4) << 4;
    const int b_row = lane & 7;
    const int b_cb  = ((lane >> 3) & 1) << 4;

    load_chunk(0, 0);
    asm volatile("cp.async.commit_group;" ::: "memory");

    for (int c = 0; c < GK_CH; c++) {
        const int s = c & 1;
        if (c + 1 < GK_CH) {
            load_chunk(c + 1, s ^ 1);
            asm volatile("cp.async.commit_group;" ::: "memory");
            asm volatile("cp.async.wait_group 1;" ::: "memory");
        } else {
            asm volatile("cp.async.wait_group 0;" ::: "memory");
        }
        __syncthreads();

        const uint32_t stg = sbase + (uint32_t)s * GT_STG;
        const uint32_t tAh = stg, tAl = stg + GT_TILE;
        const uint32_t tBh = stg + 2 * GT_TILE, tBl = stg + 3 * GT_TILE;

        #pragma unroll
        for (int ks = 0; ks < 2; ks++) {
            const int kb = ks << 5;
            uint32_t ah[4][4], al[4][4], bh[4][2], bl[4][2];
            #pragma unroll
            for (int mt = 0; mt < 4; mt++) {
                const uint32_t ro = (uint32_t)((wm * 64 + mt * 16 + a_row) * 80 + kb + a_cb);
                ldsm4(ah[mt], tAh + ro);
                ldsm4(al[mt], tAl + ro);
            }
            #pragma unroll
            for (int nt = 0; nt < 4; nt++) {
                const uint32_t ro = (uint32_t)((wn * 32 + nt * 8 + b_row) * 80 + kb + b_cb);
                ldsm2(bh[nt], tBh + ro);
                ldsm2(bl[nt], tBl + ro);
            }
            #pragma unroll
            for (int mt = 0; mt < 4; mt++)
                #pragma unroll
                for (int nt = 0; nt < 4; nt++) {
                    mma16816(acc[mt][nt], ah[mt], bh[nt]);
                    mma16816(acc[mt][nt], ah[mt], bl[nt]);
                    mma16816(acc[mt][nt], al[mt], bh[nt]);
                }
        }
        __syncthreads();
    }

    #pragma unroll
    for (int mt = 0; mt < 4; mt++) {
        const int ra = row0 + wm * 64 + mt * 16 + g;
        const int rb = ra + 8;
        #pragma unroll
        for (int nt = 0; nt < 4; nt++) {
            const int col = col0 + wn * 32 + nt * 8 + 2 * t;
            const float b0 = bias[col], b1 = bias[col + 1];
            float v0 = acc[mt][nt][0] + b0, v1 = acc[mt][nt][1] + b1;
            float v2 = acc[mt][nt][2] + b0, v3 = acc[mt][nt][3] + b1;
            if (MODE == 0) {
                *(float2*)(C + (size_t)ra * N + col) = make_float2(v0, v1);
                *(float2*)(C + (size_t)rb * N + col) = make_float2(v2, v3);
            } else {
                const int slice = col >> 10, hh = (col >> 6) & 15, dd = col & 63;
                if (slice == 0) { v0 *= 0.125f; v1 *= 0.125f; v2 *= 0.125f; v3 *= 0.125f; }
                __nv_bfloat16* oh = (slice == 0) ? qh : (slice == 1) ? kh : vh;
                __nv_bfloat16* ol = (slice == 0) ? ql : (slice == 1) ? kl : vl;
                const int ba = ra >> 11, pa = ra & 2047;
                const size_t oa = ((size_t)(ba * H_SZ + hh) * P_SZ + pa) * 64 + dd;
                uint32_t hu, lu;
                split2(v0, v1, hu, lu);
                *(uint32_t*)(oh + oa) = hu; *(uint32_t*)(ol + oa) = lu;
                split2(v2, v3, hu, lu);
                *(uint32_t*)(oh + oa + 512) = hu; *(uint32_t*)(ol + oa + 512) = lu;
            }
        }
    }
}

// ---------------- tensor-core flash attention ------------------------------
// CTA: (qt, bh). 64 q-rows, kv tiles of 64. 4 warps (warp w: rows 16w..16w+15).
// smem rows padded to 144B (72 halfs): conflict-free ldmatrix at 8-row phases.
#define AT_ROWB 144
#define AT_TILE 9216            // 64 rows * 144B
#define AT_STG  (4 * AT_TILE)   // Kh,Kl,Vh,Vl
#define AT_KV0  (2 * AT_TILE)   // after Qh,Ql
#define AT_SMEM (2 * AT_TILE + 2 * AT_STG)   // 92160

__global__ __launch_bounds__(128) void attn_mma_kernel(
    const __nv_bfloat16* __restrict__ qh, const __nv_bfloat16* __restrict__ ql,
    const __nv_bfloat16* __restrict__ kh, const __nv_bfloat16* __restrict__ kl,
    const __nv_bfloat16* __restrict__ vh, const __nv_bfloat16* __restrict__ vl,
    __nv_bfloat16* __restrict__ zh, __nv_bfloat16* __restrict__ zl)
{
    extern __shared__ char smraw[];
    const uint32_t sb = smem_u32(smraw);
    const int tid = threadIdx.x, w = tid >> 5, lane = tid & 31;
    const int g = lane >> 2, t = lane & 3;
    const int qt = blockIdx.x, bh = blockIdx.y;
    const int q0 = qt << 6;
    const size_t hb = (size_t)bh * P_SZ * 64;

    {   // Q hi/lo tile
        const __nv_bfloat16* Qh = qh + hb + (size_t)q0 * 64;
        const __nv_bfloat16* Ql = ql + hb + (size_t)q0 * 64;
        #pragma unroll
        for (int it = 0; it < 4; it++) {
            int id = it * 128 + tid, r = id >> 3, c = id & 7;
            cpasync16(sb + (uint32_t)(r * AT_ROWB + c * 16), Qh + r * 64 + c * 8);
            cpasync16(sb + AT_TILE + (uint32_t)(r * AT_ROWB + c * 16), Ql + r * 64 + c * 8);
        }
    }
    const __nv_bfloat16* kvsrc[4] = {kh + hb, kl + hb, vh + hb, vl + hb};
    auto load_kv = [&](int kv, int s) {
        const uint32_t stg = sb + AT_KV0 + (uint32_t)s * AT_STG;
        const size_t rb = (size_t)(kv << 6) * 64;
        #pragma unroll
        for (int a = 0; a < 4; a++)
            #pragma unroll
            for (int it = 0; it < 4; it++) {
                int id = it * 128 + tid, r = id >> 3, c = id & 7;
                cpasync16(stg + (uint32_t)(a * AT_TILE + r * AT_ROWB + c * 16),
                          kvsrc[a] + rb + r * 64 + c * 8);
            }
    };
    load_kv(0, 0);
    asm volatile("cp.async.commit_group;" ::: "memory");

    uint32_t qhf[4][4], qlf[4][4];
    float oacc[8][4] = {};
    float m0 = -1e30f, m1 = -1e30f, l0 = 0.f, l1 = 0.f;
    const int arow = (lane & 7) + ((lane >> 3) & 1) * 8;
    const int achk = lane >> 4;

    for (int kv = 0; kv <= qt; kv++) {
        const int s = kv & 1;
        if (kv < qt) {
            load_kv(kv + 1, s ^ 1);
            asm volatile("cp.async.commit_group;" ::: "memory");
            asm volatile("cp.async.wait_group 1;" ::: "memory");
        } else {
            asm volatile("cp.async.wait_group 0;" ::: "memory");
        }
        __syncthreads();
        if (kv == 0) {
            #pragma unroll
            for (int ks = 0; ks < 4; ks++) {
                uint32_t ad = sb + (uint32_t)((16 * w + arow) * AT_ROWB + (2 * ks + achk) * 16);
                ldsm4(qhf[ks], ad);
                ldsm4(qlf[ks], ad + AT_TILE);
            }
        }
        const uint32_t kb = sb + AT_KV0 + (uint32_t)s * AT_STG;

        // ---- S = Q K^T (split 3-term) ----
        float sacc[8][4] = {};
        #pragma unroll
        for (int j = 0; j < 8; j++) {
            #pragma unroll
            for (int cp = 0; cp < 2; cp++) {
                uint32_t khf[4], klf[4];
                uint32_t ad = kb + (uint32_t)((8 * j + (lane & 7)) * AT_ROWB +
                                              (4 * cp + (lane >> 3)) * 16);
                ldsm4(khf, ad);
                ldsm4(klf, ad + AT_TILE);
                mma16816(sacc[j], qhf[2 * cp], &khf[0]);
                mma16816(sacc[j], qhf[2 * cp], &klf[0]);
                mma16816(sacc[j], qlf[2 * cp], &khf[0]);
                mma16816(sacc[j], qhf[2 * cp + 1], &khf[2]);
                mma16816(sacc[j], qhf[2 * cp + 1], &klf[2]);
                mma16816(sacc[j], qlf[2 * cp + 1], &khf[2]);
            }
        }

        // ---- causal mask (diag tile) ----
        if (kv == qt) {
            const int lr0 = 16 * w + g;
            #pragma unroll
            for (int j = 0; j < 8; j++) {
                const int c0 = 8 * j + 2 * t;
                if (c0     > lr0)     sacc[j][0] = -1e30f;
                if (c0 + 1 > lr0)     sacc[j][1] = -1e30f;
                if (c0     > lr0 + 8) sacc[j][2] = -1e30f;
                if (c0 + 1 > lr0 + 8) sacc[j][3] = -1e30f;
            }
        }

        // ---- online softmax (rows g, g+8; stats over 4-lane t-groups) ----
        float mx0 = -1e30f, mx1 = -1e30f;
        #pragma unroll
        for (int j = 0; j < 8; j++) {
            mx0 = fmaxf(mx0, fmaxf(sacc[j][0], sacc[j][1]));
            mx1 = fmaxf(mx1, fmaxf(sacc[j][2], sacc[j][3]));
        }
        mx0 = fmaxf(mx0, __shfl_xor_sync(0xffffffffu, mx0, 1));
        mx0 = fmaxf(mx0, __shfl_xor_sync(0xffffffffu, mx0, 2));
        mx1 = fmaxf(mx1, __shfl_xor_sync(0xffffffffu, mx1, 1));
        mx1 = fmaxf(mx1, __shfl_xor_sync(0xffffffffu, mx1, 2));
        const float mn0 = fmaxf(m0, mx0), mn1 = fmaxf(m1, mx1);
        const float al0 = __expf(m0 - mn0), al1 = __expf(m1 - mn1);
        float sum0 = 0.f, sum1 = 0.f;
        #pragma unroll
        for (int j = 0; j < 8; j++) {
            sacc[j][0] = __expf(sacc[j][0] - mn0);
            sacc[j][1] = __expf(sacc[j][1] - mn0);
            sacc[j][2] = __expf(sacc[j][2] - mn1);
            sacc[j][3] = __expf(sacc[j][3] - mn1);
            sum0 += sacc[j][0] + sacc[j][1];
            sum1 += sacc[j][2] + sacc[j][3];
        }
        sum0 += __shfl_xor_sync(0xffffffffu, sum0, 1);
        sum0 += __shfl_xor_sync(0xffffffffu, sum0, 2);
        sum1 += __shfl_xor_sync(0xffffffffu, sum1, 1);
        sum1 += __shfl_xor_sync(0xffffffffu, sum1, 2);
        l0 = l0 * al0 + sum0; m0 = mn0;
        l1 = l1 * al1 + sum1; m1 = mn1;
        #pragma unroll
        for (int j = 0; j < 8; j++) {
            oacc[j][0] *= al0; oacc[j][1] *= al0;
            oacc[j][2] *= al1; oacc[j][3] *= al1;
        }

        // ---- P fragments (A-frag layout) from S accumulators, split hi/lo --
        uint32_t pah[4][4], pal[4][4];
        #pragma unroll
        for (int s2 = 0; s2 < 4; s2++) {
            split2(sacc[2 * s2][0],     sacc[2 * s2][1],     pah[s2][0], pal[s2][0]);
            split2(sacc[2 * s2][2],     sacc[2 * s2][3],     pah[s2][1], pal[s2][1]);
            split2(sacc[2 * s2 + 1][0], sacc[2 * s2 + 1][1], pah[s2][2], pal[s2][2]);
            split2(sacc[2 * s2 + 1][2], sacc[2 * s2 + 1][3], pah[s2][3], pal[s2][3]);
        }

        // ---- O += P V (split 3-term), V via ldmatrix.trans ----
        #pragma unroll
        for (int jp = 0; jp < 4; jp++) {
            #pragma unroll
            for (int s2 = 0; s2 < 4; s2++) {
                uint32_t vhf[4], vlf[4];
                uint32_t ad = kb + 2 * AT_TILE +
                    (uint32_t)((16 * s2 + (lane & 15)) * AT_ROWB + (2 * jp + (lane >> 4)) * 16);
                ldsm4t(vhf, ad);
                ldsm4t(vlf, ad + AT_TILE);
                mma16816(oacc[2 * jp],     pah[s2], &vhf[0]);
                mma16816(oacc[2 * jp],     pah[s2], &vlf[0]);
                mma16816(oacc[2 * jp],     pal[s2], &vhf[0]);
                mma16816(oacc[2 * jp + 1], pah[s2], &vhf[2]);
                mma16816(oacc[2 * jp + 1], pah[s2], &vlf[2]);
                mma16816(oacc[2 * jp + 1], pal[s2], &vhf[2]);
            }
        }
        __syncthreads();
    }

    // ---- epilogue: z rows as bf16 hi/lo (proj GEMM A-operand layout) ----
    const float i0 = 1.f / l0, i1 = 1.f / l1;
    const int b = bh >> 4, h = bh & 15;
    const size_t r0 = (size_t)b * P_SZ + q0 + 16 * w + g;
    #pragma unroll
    for (int j = 0; j < 8; j++) {
        const int zc = h * 64 + 8 * j + 2 * t;
        uint32_t hu, lu;
        split2(oacc[j][0] * i0, oacc[j][1] * i0, hu, lu);
        *(uint32_t*)(zh + r0 * K_SZ + zc) = hu;
        *(uint32_t*)(zl + r0 * K_SZ + zc) = lu;
        split2(oacc[j][2] * i1, oacc[j][3] * i1, hu, lu);
        *(uint32_t*)(zh + (r0 + 8) * K_SZ + zc) = hu;
        *(uint32_t*)(zl + (r0 + 8) * K_SZ + zc) = lu;
    }
}

// ---------------------------------------------------------------------------
extern "C" void kernel_launch(void* const* d_in, const int* in_sizes, int n_in,
                              void* d_out, int out_size)
{
    (void)in_sizes; (void)n_in; (void)out_size;
    const float* x      = (const float*)d_in[0];
    const float* W_attn = (const float*)d_in[1];
    const float* b_attn = (const float*)d_in[2];
    const float* W_proj = (const float*)d_in[3];
    const float* b_proj = (const float*)d_in[4];
    float* out = (float*)d_out;

    __nv_bfloat16 *xhi, *xlo, *wah, *wal, *wph, *wpl;
    __nv_bfloat16 *qh, *ql, *kh, *kl, *vh, *vl, *zh, *zl;
    cudaGetSymbolAddress((void**)&xhi, g_xhi);
    cudaGetSymbolAddress((void**)&xlo, g_xlo);
    cudaGetSymbolAddress((void**)&wah, g_wah);
    cudaGetSymbolAddress((void**)&wal, g_wal);
    cudaGetSymbolAddress((void**)&wph, g_wph);
    cudaGetSymbolAddress((void**)&wpl, g_wpl);
    cudaGetSymbolAddress((void**)&qh,  g_qh);
    cudaGetSymbolAddress((void**)&ql,  g_ql);
    cudaGetSymbolAddress((void**)&kh,  g_kh);
    cudaGetSymbolAddress((void**)&kl,  g_kl);
    cudaGetSymbolAddress((void**)&vh,  g_vh);
    cudaGetSymbolAddress((void**)&vl,  g_vl);
    cudaGetSymbolAddress((void**)&zh,  g_zh);
    cudaGetSymbolAddress((void**)&zl,  g_zl);

    cudaFuncSetAttribute(gemm_mma_kernel<0>,
                         cudaFuncAttributeMaxDynamicSharedMemorySize, GT_SMEM);
    cudaFuncSetAttribute(gemm_mma_kernel<1>,
                         cudaFuncAttributeMaxDynamicSharedMemorySize, GT_SMEM);
    cudaFuncSetAttribute(attn_mma_kernel,
                         cudaFuncAttributeMaxDynamicSharedMemorySize, AT_SMEM);

    // 0) conversions
    split_kernel<<<(R_SZ * K_SZ / 4 + 255) / 256, 256>>>(x, xhi, xlo, R_SZ * K_SZ / 4);
    tsplit_kernel<<<dim3(N3_SZ / 32, K_SZ / 32), 256>>>(W_attn, wah, wal, K_SZ, N3_SZ);
    tsplit_kernel<<<dim3(M_SZ / 32, K_SZ / 32), 256>>>(W_proj, wph, wpl, K_SZ, M_SZ);

    // 1) QKV projection, epilogue -> split per-head Q/K/V
    gemm_mma_kernel<1><<<dim3(N3_SZ / 128, R_SZ / 128), 256, GT_SMEM>>>(
        xhi, xlo, wah, wal, b_attn, nullptr, N3_SZ, qh, ql, kh, kl, vh, vl);

    // 2) tensor-core causal flash attention -> split z
    attn_mma_kernel<<<dim3(P_SZ / 64, BH_SZ), 128, AT_SMEM>>>(
        qh, ql, kh, kl, vh, vl, zh, zl);

    // 3) output projection
    gemm_mma_kernel<0><<<dim3(M_SZ / 128, R_SZ / 128), 256, GT_SMEM>>>(
        zh, zl, wph, wpl, b_proj, out, M_SZ,
        nullptr, nullptr, nullptr, nullptr, nullptr, nullptr);
}

// round 5
// speedup vs baseline: 2.5510x; 1.4149x over previous
#include <cuda_runtime.h>
#include <cuda_bf16.h>
#include <cstdint>
#include <string.h>
#include <math.h>

#define B_SZ 2
#define P_SZ 2048
#define M_SZ 1024
#define H_SZ 16
#define D_SZ 64
#define N3_SZ 3072
#define R_SZ (B_SZ * P_SZ)      // 4096
#define K_SZ M_SZ               // 1024
#define BH_SZ (B_SZ * H_SZ)     // 32

// ---------------- scratch (__device__ globals) -----------------------------
__device__ __nv_bfloat16 g_xhi[(size_t)R_SZ * K_SZ];
__device__ __nv_bfloat16 g_xlo[(size_t)R_SZ * K_SZ];
__device__ __nv_bfloat16 g_wah[(size_t)N3_SZ * K_SZ];
__device__ __nv_bfloat16 g_wal[(size_t)N3_SZ * K_SZ];
__device__ __nv_bfloat16 g_wph[(size_t)M_SZ * K_SZ];
__device__ __nv_bfloat16 g_wpl[(size_t)M_SZ * K_SZ];
__device__ __nv_bfloat16 g_qh[(size_t)BH_SZ * P_SZ * D_SZ];
__device__ __nv_bfloat16 g_ql[(size_t)BH_SZ * P_SZ * D_SZ];
__device__ __nv_bfloat16 g_kh[(size_t)BH_SZ * P_SZ * D_SZ];
__device__ __nv_bfloat16 g_kl[(size_t)BH_SZ * P_SZ * D_SZ];
__device__ __nv_bfloat16 g_vh[(size_t)BH_SZ * P_SZ * D_SZ];
__device__ __nv_bfloat16 g_vl[(size_t)BH_SZ * P_SZ * D_SZ];
__device__ __nv_bfloat16 g_zh[(size_t)R_SZ * K_SZ];
__device__ __nv_bfloat16 g_zl[(size_t)R_SZ * K_SZ];

// ---------------- PTX helpers (base ISA) -----------------------------------
__device__ __forceinline__ uint32_t smem_u32(const void* p) {
    uint32_t a;
    asm("{ .reg .u64 t; cvta.to.shared.u64 t, %1; cvt.u32.u64 %0, t; }" : "=r"(a) : "l"(p));
    return a;
}
__device__ __forceinline__ void ldsm4(uint32_t* r, uint32_t addr) {
    asm volatile("ldmatrix.sync.aligned.m8n8.x4.shared.b16 {%0,%1,%2,%3}, [%4];"
                 : "=r"(r[0]), "=r"(r[1]), "=r"(r[2]), "=r"(r[3]) : "r"(addr));
}
__device__ __forceinline__ void ldsm4t(uint32_t* r, uint32_t addr) {
    asm volatile("ldmatrix.sync.aligned.m8n8.x4.trans.shared.b16 {%0,%1,%2,%3}, [%4];"
                 : "=r"(r[0]), "=r"(r[1]), "=r"(r[2]), "=r"(r[3]) : "r"(addr));
}
__device__ __forceinline__ void ldsm2(uint32_t* r, uint32_t addr) {
    asm volatile("ldmatrix.sync.aligned.m8n8.x2.shared.b16 {%0,%1}, [%2];"
                 : "=r"(r[0]), "=r"(r[1]) : "r"(addr));
}
__device__ __forceinline__ void mma16816(float* c, const uint32_t* a, const uint32_t* b) {
    asm volatile(
        "mma.sync.aligned.m16n8k16.row.col.f32.bf16.bf16.f32 "
        "{%0,%1,%2,%3}, {%4,%5,%6,%7}, {%8,%9}, {%0,%1,%2,%3};"
        : "+f"(c[0]), "+f"(c[1]), "+f"(c[2]), "+f"(c[3])
        : "r"(a[0]), "r"(a[1]), "r"(a[2]), "r"(a[3]), "r"(b[0]), "r"(b[1]));
}
__device__ __forceinline__ void cpasync16(uint32_t saddr, const void* gaddr) {
    asm volatile("cp.async.cg.shared.global [%0], [%1], 16;" :: "r"(saddr), "l"(gaddr) : "memory");
}
__device__ __forceinline__ void split2(float a, float b, uint32_t& hu, uint32_t& lu) {
    __nv_bfloat16 ha = __float2bfloat16(a), hb = __float2bfloat16(b);
    float ra = a - __bfloat162float(ha), rb = b - __bfloat162float(hb);
    __nv_bfloat162 H = __halves2bfloat162(ha, hb);
    __nv_bfloat162 L = __floats2bfloat162_rn(ra, rb);
    memcpy(&hu, &H, 4); memcpy(&lu, &L, 4);
}

// ---------------- fp32 -> bf16 hi/lo split ---------------------------------
struct alignas(8) bf16x4 { __nv_bfloat162 a, b; };

__global__ __launch_bounds__(256) void split_kernel(
    const float* __restrict__ in, __nv_bfloat16* __restrict__ hi,
    __nv_bfloat16* __restrict__ lo, int n4)
{
    int i = blockIdx.x * 256 + threadIdx.x;
    if (i >= n4) return;
    float4 v = ((const float4*)in)[i];
    float h0 = __bfloat162float(__float2bfloat16(v.x));
    float h1 = __bfloat162float(__float2bfloat16(v.y));
    float h2 = __bfloat162float(__float2bfloat16(v.z));
    float h3 = __bfloat162float(__float2bfloat16(v.w));
    bf16x4 H, L;
    H.a = __floats2bfloat162_rn(h0, h1);
    H.b = __floats2bfloat162_rn(h2, h3);
    L.a = __floats2bfloat162_rn(v.x - h0, v.y - h1);
    L.b = __floats2bfloat162_rn(v.z - h2, v.w - h3);
    ((bf16x4*)hi)[i] = H;
    ((bf16x4*)lo)[i] = L;
}

__global__ __launch_bounds__(256) void tsplit_kernel(
    const float* __restrict__ W, __nv_bfloat16* __restrict__ hi,
    __nv_bfloat16* __restrict__ lo, int K, int N)
{
    __shared__ float s[32][33];
    const int n0 = blockIdx.x * 32, k0 = blockIdx.y * 32;
    const int tx = threadIdx.x & 31, ty = threadIdx.x >> 5;
    #pragma unroll
    for (int i = 0; i < 4; i++)
        s[ty + 8 * i][tx] = W[(size_t)(k0 + ty + 8 * i) * N + n0 + tx];
    __syncthreads();
    #pragma unroll
    for (int i = 0; i < 4; i++) {
        int r = ty + 8 * i;
        float v = s[tx][r];
        float h = __bfloat162float(__float2bfloat16(v));
        size_t o = (size_t)(n0 + r) * K + k0 + tx;
        hi[o] = __float2bfloat16(h);
        lo[o] = __float2bfloat16(v - h);
    }
}

// ---------------- split-bf16 mma GEMM (3-stage cp.async pipeline) ----------
#define GK_CH   (K_SZ / 32)          // 32 chunks
#define GT_TILE 10240                // 128 rows * 80 B
#define GT_STG  (4 * GT_TILE)
#define GT_SMEM (3 * GT_STG)         // 122880 B

// Q pre-scale: 1/sqrt(64) * log2(e)  (attention softmax runs in base 2)
#define QSCALE (0.125f * 1.44269504088896f)

template<int MODE>
__global__ __launch_bounds__(256) void gemm_mma_kernel(
    const __nv_bfloat16* __restrict__ Ah, const __nv_bfloat16* __restrict__ Al,
    const __nv_bfloat16* __restrict__ Bh, const __nv_bfloat16* __restrict__ Bl,
    const float* __restrict__ bias, float* __restrict__ C, int N,
    __nv_bfloat16* __restrict__ qh, __nv_bfloat16* __restrict__ ql,
    __nv_bfloat16* __restrict__ kh, __nv_bfloat16* __restrict__ kl,
    __nv_bfloat16* __restrict__ vh, __nv_bfloat16* __restrict__ vl)
{
    extern __shared__ char smraw[];
    const uint32_t sbase = smem_u32(smraw);

    const int tid = threadIdx.x;
    const int wid = tid >> 5, lane = tid & 31;
    const int wm = wid & 1, wn = wid >> 1;
    const int g = lane >> 2, t = lane & 3;
    const int row0 = blockIdx.y << 7;
    const int col0 = blockIdx.x << 7;

    const __nv_bfloat16* srcs[4] = {Ah, Al, Bh, Bl};
    const int ldr0 = tid >> 2, ldq = tid & 3;
    const int ldr1 = (256 + tid) >> 2;

    auto load_chunk = [&](int c, int s) {
        const int k0 = c << 5;
        const uint32_t stg = sbase + (uint32_t)s * GT_STG;
        #pragma unroll
        for (int arr = 0; arr < 4; arr++) {
            const __nv_bfloat16* src = srcs[arr];
            const int rbase = (arr < 2) ? row0 : col0;
            const uint32_t tb = stg + (uint32_t)arr * GT_TILE;
            cpasync16(tb + (uint32_t)(ldr0 * 80 + ldq * 16),
                      src + (size_t)(rbase + ldr0) * K_SZ + k0 + ldq * 8);
            cpasync16(tb + (uint32_t)(ldr1 * 80 + ldq * 16),
                      src + (size_t)(rbase + ldr1) * K_SZ + k0 + ldq * 8);
        }
    };

    float acc[4][4][4] = {};
    const int a_row = lane & 15;
    const int a_cb  = (lane >> 4) << 4;
    const int b_row = lane & 7;
    const int b_cb  = ((lane >> 3) & 1) << 4;

    load_chunk(0, 0);
    asm volatile("cp.async.commit_group;" ::: "memory");
    load_chunk(1, 1);
    asm volatile("cp.async.commit_group;" ::: "memory");

    int stage = 0;
    for (int c = 0; c < GK_CH; c++) {
        asm volatile("cp.async.wait_group 1;" ::: "memory");
        __syncthreads();

        const uint32_t stg = sbase + (uint32_t)stage * GT_STG;
        const uint32_t tAh = stg, tAl = stg + GT_TILE;
        const uint32_t tBh = stg + 2 * GT_TILE, tBl = stg + 3 * GT_TILE;

        #pragma unroll
        for (int ks = 0; ks < 2; ks++) {
            const int kb = ks << 5;
            uint32_t ah[4][4], al[4][4], bh[4][2], bl[4][2];
            #pragma unroll
            for (int mt = 0; mt < 4; mt++) {
                const uint32_t ro = (uint32_t)((wm * 64 + mt * 16 + a_row) * 80 + kb + a_cb);
                ldsm4(ah[mt], tAh + ro);
                ldsm4(al[mt], tAl + ro);
            }
            #pragma unroll
            for (int nt = 0; nt < 4; nt++) {
                const uint32_t ro = (uint32_t)((wn * 32 + nt * 8 + b_row) * 80 + kb + b_cb);
                ldsm2(bh[nt], tBh + ro);
                ldsm2(bl[nt], tBl + ro);
            }
            #pragma unroll
            for (int mt = 0; mt < 4; mt++)
                #pragma unroll
                for (int nt = 0; nt < 4; nt++) {
                    mma16816(acc[mt][nt], ah[mt], bh[nt]);
                    mma16816(acc[mt][nt], ah[mt], bl[nt]);
                    mma16816(acc[mt][nt], al[mt], bh[nt]);
                }
        }
        __syncthreads();
        if (c + 2 < GK_CH) {
            load_chunk(c + 2, (c + 2) % 3);
        }
        asm volatile("cp.async.commit_group;" ::: "memory");
        stage++; if (stage == 3) stage = 0;
    }

    #pragma unroll
    for (int mt = 0; mt < 4; mt++) {
        const int ra = row0 + wm * 64 + mt * 16 + g;
        const int rb = ra + 8;
        #pragma unroll
        for (int nt = 0; nt < 4; nt++) {
            const int col = col0 + wn * 32 + nt * 8 + 2 * t;
            const float b0 = bias[col], b1 = bias[col + 1];
            float v0 = acc[mt][nt][0] + b0, v1 = acc[mt][nt][1] + b1;
            float v2 = acc[mt][nt][2] + b0, v3 = acc[mt][nt][3] + b1;
            if (MODE == 0) {
                *(float2*)(C + (size_t)ra * N + col) = make_float2(v0, v1);
                *(float2*)(C + (size_t)rb * N + col) = make_float2(v2, v3);
            } else {
                const int slice = col >> 10, hh = (col >> 6) & 15, dd = col & 63;
                if (slice == 0) { v0 *= QSCALE; v1 *= QSCALE; v2 *= QSCALE; v3 *= QSCALE; }
                __nv_bfloat16* oh = (slice == 0) ? qh : (slice == 1) ? kh : vh;
                __nv_bfloat16* ol = (slice == 0) ? ql : (slice == 1) ? kl : vl;
                const int ba = ra >> 11, pa = ra & 2047;
                const size_t oa = ((size_t)(ba * H_SZ + hh) * P_SZ + pa) * 64 + dd;
                uint32_t hu, lu;
                split2(v0, v1, hu, lu);
                *(uint32_t*)(oh + oa) = hu; *(uint32_t*)(ol + oa) = lu;
                split2(v2, v3, hu, lu);
                *(uint32_t*)(oh + oa + 512) = hu; *(uint32_t*)(ol + oa + 512) = lu;
            }
        }
    }
}

// ---------------- tensor-core flash attention (128 q-rows / CTA) -----------
#define AT_ROWB 144
#define AT_QTILE (128 * AT_ROWB)        // 18432
#define AT_KTILE (64 * AT_ROWB)         // 9216
#define AT_KV0   (2 * AT_QTILE)         // 36864
#define AT_STG   (4 * AT_KTILE)         // 36864
#define AT_SMEM  (AT_KV0 + 2 * AT_STG)  // 110592

__global__ __launch_bounds__(256) void attn_mma_kernel(
    const __nv_bfloat16* __restrict__ qh, const __nv_bfloat16* __restrict__ ql,
    const __nv_bfloat16* __restrict__ kh, const __nv_bfloat16* __restrict__ kl,
    const __nv_bfloat16* __restrict__ vh, const __nv_bfloat16* __restrict__ vl,
    __nv_bfloat16* __restrict__ zh, __nv_bfloat16* __restrict__ zl)
{
    extern __shared__ char smraw[];
    const uint32_t sb = smem_u32(smraw);
    const int tid = threadIdx.x, w = tid >> 5, lane = tid & 31;
    const int g = lane >> 2, t = lane & 3;
    const int qt = blockIdx.x, bh = blockIdx.y;
    const int q0 = qt << 7;
    const size_t hb = (size_t)bh * P_SZ * 64;

    {   // Q hi/lo tile: 128 rows x 64 cols
        const __nv_bfloat16* Qh = qh + hb + (size_t)q0 * 64;
        const __nv_bfloat16* Ql = ql + hb + (size_t)q0 * 64;
        #pragma unroll
        for (int it = 0; it < 4; it++) {
            int id = it * 256 + tid, r = id >> 3, c = id & 7;
            cpasync16(sb + (uint32_t)(r * AT_ROWB + c * 16), Qh + r * 64 + c * 8);
            cpasync16(sb + AT_QTILE + (uint32_t)(r * AT_ROWB + c * 16), Ql + r * 64 + c * 8);
        }
    }
    const __nv_bfloat16* kvsrc[4] = {kh + hb, kl + hb, vh + hb, vl + hb};
    auto load_kv = [&](int kvt, int s) {
        const uint32_t stg = sb + AT_KV0 + (uint32_t)s * AT_STG;
        const size_t rb = (size_t)(kvt << 6) * 64;
        #pragma unroll
        for (int a = 0; a < 4; a++)
            #pragma unroll
            for (int it = 0; it < 2; it++) {
                int id = it * 256 + tid, r = id >> 3, c = id & 7;
                cpasync16(stg + (uint32_t)(a * AT_KTILE + r * AT_ROWB + c * 16),
                          kvsrc[a] + rb + r * 64 + c * 8);
            }
    };
    const int ntiles = 2 * qt + 2;
    load_kv(0, 0);
    asm volatile("cp.async.commit_group;" ::: "memory");

    uint32_t qhf[4][4], qlf[4][4];
    float oacc[8][4] = {};
    float m0 = -1e30f, m1 = -1e30f, l0 = 0.f, l1 = 0.f;
    const int arow = (lane & 7) + ((lane >> 3) & 1) * 8;
    const int achk = lane >> 4;
    const int wrow_min = q0 + 16 * w;
    const int wrow_max = wrow_min + 15;

    for (int kvt = 0; kvt < ntiles; kvt++) {
        const int s = kvt & 1;
        if (kvt + 1 < ntiles) {
            load_kv(kvt + 1, s ^ 1);
            asm volatile("cp.async.commit_group;" ::: "memory");
            asm volatile("cp.async.wait_group 1;" ::: "memory");
        } else {
            asm volatile("cp.async.wait_group 0;" ::: "memory");
        }
        __syncthreads();
        if (kvt == 0) {
            #pragma unroll
            for (int ks = 0; ks < 4; ks++) {
                uint32_t ad = sb + (uint32_t)((16 * w + arow) * AT_ROWB + (2 * ks + achk) * 16);
                ldsm4(qhf[ks], ad);
                ldsm4(qlf[ks], ad + AT_QTILE);
            }
        }
        const int c_base = kvt << 6;
        if (c_base <= wrow_max) {
            const uint32_t kb = sb + AT_KV0 + (uint32_t)s * AT_STG;

            float sacc[8][4] = {};
            #pragma unroll
            for (int j = 0; j < 8; j++) {
                #pragma unroll
                for (int cp = 0; cp < 2; cp++) {
                    uint32_t khf[4], klf[4];
                    uint32_t ad = kb + (uint32_t)((8 * j + (lane & 7)) * AT_ROWB +
                                                  (4 * cp + (lane >> 3)) * 16);
                    ldsm4(khf, ad);
                    ldsm4(klf, ad + AT_KTILE);
                    mma16816(sacc[j], qhf[2 * cp], &khf[0]);
                    mma16816(sacc[j], qhf[2 * cp], &klf[0]);
                    mma16816(sacc[j], qlf[2 * cp], &khf[0]);
                    mma16816(sacc[j], qhf[2 * cp + 1], &khf[2]);
                    mma16816(sacc[j], qhf[2 * cp + 1], &klf[2]);
                    mma16816(sacc[j], qlf[2 * cp + 1], &khf[2]);
                }
            }

            if (c_base + 63 > wrow_min) {
                const int lr0 = wrow_min + g;
                #pragma unroll
                for (int j = 0; j < 8; j++) {
                    const int c0 = c_base + 8 * j + 2 * t;
                    if (c0     > lr0)     sacc[j][0] = -1e30f;
                    if (c0 + 1 > lr0)     sacc[j][1] = -1e30f;
                    if (c0     > lr0 + 8) sacc[j][2] = -1e30f;
                    if (c0 + 1 > lr0 + 8) sacc[j][3] = -1e30f;
                }
            }

            float mx0 = -1e30f, mx1 = -1e30f;
            #pragma unroll
            for (int j = 0; j < 8; j++) {
                mx0 = fmaxf(mx0, fmaxf(sacc[j][0], sacc[j][1]));
                mx1 = fmaxf(mx1, fmaxf(sacc[j][2], sacc[j][3]));
            }
            mx0 = fmaxf(mx0, __shfl_xor_sync(0xffffffffu, mx0, 1));
            mx0 = fmaxf(mx0, __shfl_xor_sync(0xffffffffu, mx0, 2));
            mx1 = fmaxf(mx1, __shfl_xor_sync(0xffffffffu, mx1, 1));
            mx1 = fmaxf(mx1, __shfl_xor_sync(0xffffffffu, mx1, 2));
            const float mn0 = fmaxf(m0, mx0), mn1 = fmaxf(m1, mx1);
            const float al0 = exp2f(m0 - mn0), al1 = exp2f(m1 - mn1);
            float sum0 = 0.f, sum1 = 0.f;
            #pragma unroll
            for (int j = 0; j < 8; j++) {
                sacc[j][0] = exp2f(sacc[j][0] - mn0);
                sacc[j][1] = exp2f(sacc[j][1] - mn0);
                sacc[j][2] = exp2f(sacc[j][2] - mn1);
                sacc[j][3] = exp2f(sacc[j][3] - mn1);
                sum0 += sacc[j][0] + sacc[j][1];
                sum1 += sacc[j][2] + sacc[j][3];
            }
            sum0 += __shfl_xor_sync(0xffffffffu, sum0, 1);
            sum0 += __shfl_xor_sync(0xffffffffu, sum0, 2);
            sum1 += __shfl_xor_sync(0xffffffffu, sum1, 1);
            sum1 += __shfl_xor_sync(0xffffffffu, sum1, 2);
            l0 = l0 * al0 + sum0; m0 = mn0;
            l1 = l1 * al1 + sum1; m1 = mn1;
            #pragma unroll
            for (int j = 0; j < 8; j++) {
                oacc[j][0] *= al0; oacc[j][1] *= al0;
                oacc[j][2] *= al1; oacc[j][3] *= al1;
            }

            uint32_t pah[4][4], pal[4][4];
            #pragma unroll
            for (int s2 = 0; s2 < 4; s2++) {
                split2(sacc[2 * s2][0],     sacc[2 * s2][1],     pah[s2][0], pal[s2][0]);
                split2(sacc[2 * s2][2],     sacc[2 * s2][3],     pah[s2][1], pal[s2][1]);
                split2(sacc[2 * s2 + 1][0], sacc[2 * s2 + 1][1], pah[s2][2], pal[s2][2]);
                split2(sacc[2 * s2 + 1][2], sacc[2 * s2 + 1][3], pah[s2][3], pal[s2][3]);
            }

            #pragma unroll
            for (int jp = 0; jp < 4; jp++) {
                #pragma unroll
                for (int s2 = 0; s2 < 4; s2++) {
                    uint32_t vhf[4], vlf[4];
                    uint32_t ad = kb + 2 * AT_KTILE +
                        (uint32_t)((16 * s2 + (lane & 15)) * AT_ROWB + (2 * jp + (lane >> 4)) * 16);
                    ldsm4t(vhf, ad);
                    ldsm4t(vlf, ad + AT_KTILE);
                    mma16816(oacc[2 * jp],     pah[s2], &vhf[0]);
                    mma16816(oacc[2 * jp],     pah[s2], &vlf[0]);
                    mma16816(oacc[2 * jp],     pal[s2], &vhf[0]);
                    mma16816(oacc[2 * jp + 1], pah[s2], &vhf[2]);
                    mma16816(oacc[2 * jp + 1], pah[s2], &vlf[2]);
                    mma16816(oacc[2 * jp + 1], pal[s2], &vhf[2]);
                }
            }
        }
        __syncthreads();
    }

    const float i0 = 1.f / l0, i1 = 1.f / l1;
    const int b = bh >> 4, h = bh & 15;
    const size_t r0 = (size_t)b * P_SZ + q0 + 16 * w + g;
    #pragma unroll
    for (int j = 0; j < 8; j++) {
        const int zc = h * 64 + 8 * j + 2 * t;
        uint32_t hu, lu;
        split2(oacc[j][0] * i0, oacc[j][1] * i0, hu, lu);
        *(uint32_t*)(zh + r0 * K_SZ + zc) = hu;
        *(uint32_t*)(zl + r0 * K_SZ + zc) = lu;
        split2(oacc[j][2] * i1, oacc[j][3] * i1, hu, lu);
        *(uint32_t*)(zh + (r0 + 8) * K_SZ + zc) = hu;
        *(uint32_t*)(zl + (r0 + 8) * K_SZ + zc) = lu;
    }
}

// ---------------------------------------------------------------------------
extern "C" void kernel_launch(void* const* d_in, const int* in_sizes, int n_in,
                              void* d_out, int out_size)
{
    (void)in_sizes; (void)n_in; (void)out_size;
    const float* x      = (const float*)d_in[0];
    const float* W_attn = (const float*)d_in[1];
    const float* b_attn = (const float*)d_in[2];
    const float* W_proj = (const float*)d_in[3];
    const float* b_proj = (const float*)d_in[4];
    float* out = (float*)d_out;

    __nv_bfloat16 *xhi, *xlo, *wah, *wal, *wph, *wpl;
    __nv_bfloat16 *qh, *ql, *kh, *kl, *vh, *vl, *zh, *zl;
    cudaGetSymbolAddress((void**)&xhi, g_xhi);
    cudaGetSymbolAddress((void**)&xlo, g_xlo);
    cudaGetSymbolAddress((void**)&wah, g_wah);
    cudaGetSymbolAddress((void**)&wal, g_wal);
    cudaGetSymbolAddress((void**)&wph, g_wph);
    cudaGetSymbolAddress((void**)&wpl, g_wpl);
    cudaGetSymbolAddress((void**)&qh,  g_qh);
    cudaGetSymbolAddress((void**)&ql,  g_ql);
    cudaGetSymbolAddress((void**)&kh,  g_kh);
    cudaGetSymbolAddress((void**)&kl,  g_kl);
    cudaGetSymbolAddress((void**)&vh,  g_vh);
    cudaGetSymbolAddress((void**)&vl,  g_vl);
    cudaGetSymbolAddress((void**)&zh,  g_zh);
    cudaGetSymbolAddress((void**)&zl,  g_zl);

    cudaFuncSetAttribute(gemm_mma_kernel<0>,
                         cudaFuncAttributeMaxDynamicSharedMemorySize, GT_SMEM);
    cudaFuncSetAttribute(gemm_mma_kernel<1>,
                         cudaFuncAttributeMaxDynamicSharedMemorySize, GT_SMEM);
    cudaFuncSetAttribute(attn_mma_kernel,
                         cudaFuncAttributeMaxDynamicSharedMemorySize, AT_SMEM);

    split_kernel<<<(R_SZ * K_SZ / 4 + 255) / 256, 256>>>(x, xhi, xlo, R_SZ * K_SZ / 4);
    tsplit_kernel<<<dim3(N3_SZ / 32, K_SZ / 32), 256>>>(W_attn, wah, wal, K_SZ, N3_SZ);
    tsplit_kernel<<<dim3(M_SZ / 32, K_SZ / 32), 256>>>(W_proj, wph, wpl, K_SZ, M_SZ);

    gemm_mma_kernel<1><<<dim3(N3_SZ / 128, R_SZ / 128), 256, GT_SMEM>>>(
        xhi, xlo, wah, wal, b_attn, nullptr, N3_SZ, qh, ql, kh, kl, vh, vl);

    attn_mma_kernel<<<dim3(P_SZ / 128, BH_SZ), 256, AT_SMEM>>>(
        qh, ql, kh, kl, vh, vl, zh, zl);

    gemm_mma_kernel<0><<<dim3(M_SZ / 128, R_SZ / 128), 256, GT_SMEM>>>(
        zh, zl, wph, wpl, b_proj, out, M_SZ,
        nullptr, nullptr, nullptr, nullptr, nullptr, nullptr);
}

// round 6
// speedup vs baseline: 2.8132x; 1.1028x over previous
#include <cuda_runtime.h>
#include <cuda_bf16.h>
#include <cstdint>
#include <string.h>
#include <math.h>

#define B_SZ 2
#define P_SZ 2048
#define M_SZ 1024
#define H_SZ 16
#define D_SZ 64
#define N3_SZ 3072
#define R_SZ (B_SZ * P_SZ)      // 4096
#define K_SZ M_SZ               // 1024
#define BH_SZ (B_SZ * H_SZ)     // 32

// ---------------- scratch (__device__ globals) -----------------------------
__device__ __nv_bfloat16 g_xhi[(size_t)R_SZ * K_SZ];
__device__ __nv_bfloat16 g_xlo[(size_t)R_SZ * K_SZ];
__device__ __nv_bfloat16 g_wah[(size_t)N3_SZ * K_SZ];
__device__ __nv_bfloat16 g_wal[(size_t)N3_SZ * K_SZ];
__device__ __nv_bfloat16 g_wph[(size_t)M_SZ * K_SZ];
__device__ __nv_bfloat16 g_wpl[(size_t)M_SZ * K_SZ];
__device__ __nv_bfloat16 g_qh[(size_t)BH_SZ * P_SZ * D_SZ];
__device__ __nv_bfloat16 g_ql[(size_t)BH_SZ * P_SZ * D_SZ];
__device__ __nv_bfloat16 g_kh[(size_t)BH_SZ * P_SZ * D_SZ];
__device__ __nv_bfloat16 g_kl[(size_t)BH_SZ * P_SZ * D_SZ];
__device__ __nv_bfloat16 g_vh[(size_t)BH_SZ * P_SZ * D_SZ];
__device__ __nv_bfloat16 g_vl[(size_t)BH_SZ * P_SZ * D_SZ];
__device__ __nv_bfloat16 g_zh[(size_t)R_SZ * K_SZ];
__device__ __nv_bfloat16 g_zl[(size_t)R_SZ * K_SZ];

// ---------------- PTX helpers (base ISA) -----------------------------------
__device__ __forceinline__ uint32_t smem_u32(const void* p) {
    uint32_t a;
    asm("{ .reg .u64 t; cvta.to.shared.u64 t, %1; cvt.u32.u64 %0, t; }" : "=r"(a) : "l"(p));
    return a;
}
__device__ __forceinline__ void ldsm4(uint32_t* r, uint32_t addr) {
    asm volatile("ldmatrix.sync.aligned.m8n8.x4.shared.b16 {%0,%1,%2,%3}, [%4];"
                 : "=r"(r[0]), "=r"(r[1]), "=r"(r[2]), "=r"(r[3]) : "r"(addr));
}
__device__ __forceinline__ void ldsm4t(uint32_t* r, uint32_t addr) {
    asm volatile("ldmatrix.sync.aligned.m8n8.x4.trans.shared.b16 {%0,%1,%2,%3}, [%4];"
                 : "=r"(r[0]), "=r"(r[1]), "=r"(r[2]), "=r"(r[3]) : "r"(addr));
}
__device__ __forceinline__ void mma16816(float* c, const uint32_t* a, const uint32_t* b) {
    asm volatile(
        "mma.sync.aligned.m16n8k16.row.col.f32.bf16.bf16.f32 "
        "{%0,%1,%2,%3}, {%4,%5,%6,%7}, {%8,%9}, {%0,%1,%2,%3};"
        : "+f"(c[0]), "+f"(c[1]), "+f"(c[2]), "+f"(c[3])
        : "r"(a[0]), "r"(a[1]), "r"(a[2]), "r"(a[3]), "r"(b[0]), "r"(b[1]));
}
__device__ __forceinline__ void cpasync16(uint32_t saddr, const void* gaddr) {
    asm volatile("cp.async.cg.shared.global [%0], [%1], 16;" :: "r"(saddr), "l"(gaddr) : "memory");
}
__device__ __forceinline__ void split2(float a, float b, uint32_t& hu, uint32_t& lu) {
    __nv_bfloat16 ha = __float2bfloat16(a), hb = __float2bfloat16(b);
    float ra = a - __bfloat162float(ha), rb = b - __bfloat162float(hb);
    __nv_bfloat162 H = __halves2bfloat162(ha, hb);
    __nv_bfloat162 L = __floats2bfloat162_rn(ra, rb);
    memcpy(&hu, &H, 4); memcpy(&lu, &L, 4);
}

// ---------------- fp32 -> bf16 hi/lo split ---------------------------------
struct alignas(8) bf16x4 { __nv_bfloat162 a, b; };

__global__ __launch_bounds__(256) void split_kernel(
    const float* __restrict__ in, __nv_bfloat16* __restrict__ hi,
    __nv_bfloat16* __restrict__ lo, int n4)
{
    int i = blockIdx.x * 256 + threadIdx.x;
    if (i >= n4) return;
    float4 v = ((const float4*)in)[i];
    float h0 = __bfloat162float(__float2bfloat16(v.x));
    float h1 = __bfloat162float(__float2bfloat16(v.y));
    float h2 = __bfloat162float(__float2bfloat16(v.z));
    float h3 = __bfloat162float(__float2bfloat16(v.w));
    bf16x4 H, L;
    H.a = __floats2bfloat162_rn(h0, h1);
    H.b = __floats2bfloat162_rn(h2, h3);
    L.a = __floats2bfloat162_rn(v.x - h0, v.y - h1);
    L.b = __floats2bfloat162_rn(v.z - h2, v.w - h3);
    ((bf16x4*)hi)[i] = H;
    ((bf16x4*)lo)[i] = L;
}

__global__ __launch_bounds__(256) void tsplit_kernel(
    const float* __restrict__ W, __nv_bfloat16* __restrict__ hi,
    __nv_bfloat16* __restrict__ lo, int K, int N)
{
    __shared__ float s[32][33];
    const int n0 = blockIdx.x * 32, k0 = blockIdx.y * 32;
    const int tx = threadIdx.x & 31, ty = threadIdx.x >> 5;
    #pragma unroll
    for (int i = 0; i < 4; i++)
        s[ty + 8 * i][tx] = W[(size_t)(k0 + ty + 8 * i) * N + n0 + tx];
    __syncthreads();
    #pragma unroll
    for (int i = 0; i < 4; i++) {
        int r = ty + 8 * i;
        float v = s[tx][r];
        float h = __bfloat162float(__float2bfloat16(v));
        size_t o = (size_t)(n0 + r) * K + k0 + tx;
        hi[o] = __float2bfloat16(h);
        lo[o] = __float2bfloat16(v - h);
    }
}

// ---------------- split-bf16 mma GEMM: 4 warps, 64x64 warp tile ------------
#define GK_CH   (K_SZ / 32)          // 32 chunks
#define GT_TILE 10240                // 128 rows * 80 B
#define GT_STG  (4 * GT_TILE)
#define GT_SMEM (2 * GT_STG)         // 81920 B (2-stage)

// Q pre-scale: 1/sqrt(64) * log2(e)  (softmax runs base-2)
#define QSCALE (0.125f * 1.44269504088896f)

template<int MODE>
__global__ __launch_bounds__(128) void gemm_mma_kernel(
    const __nv_bfloat16* __restrict__ Ah, const __nv_bfloat16* __restrict__ Al,
    const __nv_bfloat16* __restrict__ Bh, const __nv_bfloat16* __restrict__ Bl,
    const float* __restrict__ bias, float* __restrict__ C, int N,
    __nv_bfloat16* __restrict__ qh, __nv_bfloat16* __restrict__ ql,
    __nv_bfloat16* __restrict__ kh, __nv_bfloat16* __restrict__ kl,
    __nv_bfloat16* __restrict__ vh, __nv_bfloat16* __restrict__ vl)
{
    extern __shared__ char smraw[];
    const uint32_t sbase = smem_u32(smraw);

    const int tid = threadIdx.x;
    const int wid = tid >> 5, lane = tid & 31;
    const int wm = wid & 1, wn = wid >> 1;          // wn in {0,1}: 64 cols
    const int g = lane >> 2, t = lane & 3;
    const int row0 = blockIdx.y << 7;
    const int col0 = blockIdx.x << 7;

    const __nv_bfloat16* srcs[4] = {Ah, Al, Bh, Bl};

    auto load_chunk = [&](int c, int s) {
        const int k0 = c << 5;
        const uint32_t stg = sbase + (uint32_t)s * GT_STG;
        #pragma unroll
        for (int arr = 0; arr < 4; arr++) {
            const __nv_bfloat16* src = srcs[arr];
            const int rbase = (arr < 2) ? row0 : col0;
            const uint32_t tb = stg + (uint32_t)arr * GT_TILE;
            #pragma unroll
            for (int it = 0; it < 4; it++) {
                int id = it * 128 + tid, r = id >> 2, q = id & 3;
                cpasync16(tb + (uint32_t)(r * 80 + q * 16),
                          src + (size_t)(rbase + r) * K_SZ + k0 + q * 8);
            }
        }
    };

    float acc[4][8][4] = {};
    const int a_row = lane & 15;
    const int a_cb  = (lane >> 4) << 4;
    const int b2_row = (lane & 7) + ((lane >> 4) << 3);   // rows 0-15 across lane pairs
    const int b2_cb  = ((lane >> 3) & 1) << 4;

    load_chunk(0, 0);
    asm volatile("cp.async.commit_group;" ::: "memory");

    for (int c = 0; c < GK_CH; c++) {
        const int s = c & 1;
        if (c + 1 < GK_CH) {
            load_chunk(c + 1, s ^ 1);
            asm volatile("cp.async.commit_group;" ::: "memory");
            asm volatile("cp.async.wait_group 1;" ::: "memory");
        } else {
            asm volatile("cp.async.wait_group 0;" ::: "memory");
        }
        __syncthreads();

        const uint32_t stg = sbase + (uint32_t)s * GT_STG;
        const uint32_t tAh = stg, tAl = stg + GT_TILE;
        const uint32_t tBh = stg + 2 * GT_TILE, tBl = stg + 3 * GT_TILE;

        #pragma unroll
        for (int ks = 0; ks < 2; ks++) {
            const int kb = ks << 5;
            uint32_t ah[4][4], al[4][4];
            #pragma unroll
            for (int mt = 0; mt < 4; mt++) {
                const uint32_t ro = (uint32_t)((wm * 64 + mt * 16 + a_row) * 80 + kb + a_cb);
                ldsm4(ah[mt], tAh + ro);
                ldsm4(al[mt], tAl + ro);
            }
            #pragma unroll
            for (int np = 0; np < 4; np++) {
                uint32_t bh4[4], bl4[4];
                const uint32_t ro = (uint32_t)((wn * 64 + np * 16 + b2_row) * 80 + kb + b2_cb);
                ldsm4(bh4, tBh + ro);
                ldsm4(bl4, tBl + ro);
                #pragma unroll
                for (int mt = 0; mt < 4; mt++) {
                    mma16816(acc[mt][2 * np],     ah[mt], &bh4[0]);
                    mma16816(acc[mt][2 * np],     ah[mt], &bl4[0]);
                    mma16816(acc[mt][2 * np],     al[mt], &bh4[0]);
                    mma16816(acc[mt][2 * np + 1], ah[mt], &bh4[2]);
                    mma16816(acc[mt][2 * np + 1], ah[mt], &bl4[2]);
                    mma16816(acc[mt][2 * np + 1], al[mt], &bh4[2]);
                }
            }
        }
        __syncthreads();
    }

    #pragma unroll
    for (int mt = 0; mt < 4; mt++) {
        const int ra = row0 + wm * 64 + mt * 16 + g;
        const int rb = ra + 8;
        #pragma unroll
        for (int nt = 0; nt < 8; nt++) {
            const int col = col0 + wn * 64 + nt * 8 + 2 * t;
            const float b0 = bias[col], b1 = bias[col + 1];
            float v0 = acc[mt][nt][0] + b0, v1 = acc[mt][nt][1] + b1;
            float v2 = acc[mt][nt][2] + b0, v3 = acc[mt][nt][3] + b1;
            if (MODE == 0) {
                *(float2*)(C + (size_t)ra * N + col) = make_float2(v0, v1);
                *(float2*)(C + (size_t)rb * N + col) = make_float2(v2, v3);
            } else {
                const int slice = col >> 10, hh = (col >> 6) & 15, dd = col & 63;
                if (slice == 0) { v0 *= QSCALE; v1 *= QSCALE; v2 *= QSCALE; v3 *= QSCALE; }
                __nv_bfloat16* oh = (slice == 0) ? qh : (slice == 1) ? kh : vh;
                __nv_bfloat16* ol = (slice == 0) ? ql : (slice == 1) ? kl : vl;
                const int ba = ra >> 11, pa = ra & 2047;
                const size_t oa = ((size_t)(ba * H_SZ + hh) * P_SZ + pa) * 64 + dd;
                uint32_t hu, lu;
                split2(v0, v1, hu, lu);
                *(uint32_t*)(oh + oa) = hu; *(uint32_t*)(ol + oa) = lu;
                split2(v2, v3, hu, lu);
                *(uint32_t*)(oh + oa + 512) = hu; *(uint32_t*)(ol + oa + 512) = lu;
            }
        }
    }
}

// ---------------- tensor-core flash attention: 4 warps x 32 q-rows ---------
#define AT_ROWB 144
#define AT_QTILE (128 * AT_ROWB)        // 18432
#define AT_KTILE (64 * AT_ROWB)         // 9216
#define AT_KV0   (2 * AT_QTILE)         // 36864
#define AT_STG   (4 * AT_KTILE)         // 36864
#define AT_SMEM  (AT_KV0 + 2 * AT_STG)  // 110592

__global__ __launch_bounds__(128) void attn_mma_kernel(
    const __nv_bfloat16* __restrict__ qh, const __nv_bfloat16* __restrict__ ql,
    const __nv_bfloat16* __restrict__ kh, const __nv_bfloat16* __restrict__ kl,
    const __nv_bfloat16* __restrict__ vh, const __nv_bfloat16* __restrict__ vl,
    __nv_bfloat16* __restrict__ zh, __nv_bfloat16* __restrict__ zl)
{
    extern __shared__ char smraw[];
    const uint32_t sb = smem_u32(smraw);
    const int tid = threadIdx.x, w = tid >> 5, lane = tid & 31;
    const int g = lane >> 2, t = lane & 3;
    const int qt = blockIdx.x, bh = blockIdx.y;
    const int q0 = qt << 7;
    const size_t hb = (size_t)bh * P_SZ * 64;

    {   // Q hi/lo tile: 128 rows x 64 cols
        const __nv_bfloat16* Qh = qh + hb + (size_t)q0 * 64;
        const __nv_bfloat16* Ql = ql + hb + (size_t)q0 * 64;
        #pragma unroll
        for (int it = 0; it < 8; it++) {
            int id = it * 128 + tid, r = id >> 3, c = id & 7;
            cpasync16(sb + (uint32_t)(r * AT_ROWB + c * 16), Qh + r * 64 + c * 8);
            cpasync16(sb + AT_QTILE + (uint32_t)(r * AT_ROWB + c * 16), Ql + r * 64 + c * 8);
        }
    }
    const __nv_bfloat16* kvsrc[4] = {kh + hb, kl + hb, vh + hb, vl + hb};
    auto load_kv = [&](int kvt, int s) {
        const uint32_t stg = sb + AT_KV0 + (uint32_t)s * AT_STG;
        const size_t rb = (size_t)(kvt << 6) * 64;
        #pragma unroll
        for (int a = 0; a < 4; a++)
            #pragma unroll
            for (int it = 0; it < 4; it++) {
                int id = it * 128 + tid, r = id >> 3, c = id & 7;
                cpasync16(stg + (uint32_t)(a * AT_KTILE + r * AT_ROWB + c * 16),
                          kvsrc[a] + rb + r * 64 + c * 8);
            }
    };
    const int ntiles = 2 * qt + 2;
    load_kv(0, 0);
    asm volatile("cp.async.commit_group;" ::: "memory");

    uint32_t qhf[2][4][4], qlf[2][4][4];
    float oacc[2][8][4] = {};
    float mrow[2][2], lrow[2][2];
    #pragma unroll
    for (int mt = 0; mt < 2; mt++) {
        mrow[mt][0] = -1e30f; mrow[mt][1] = -1e30f;
        lrow[mt][0] = 0.f;    lrow[mt][1] = 0.f;
    }
    const int arow = (lane & 7) + ((lane >> 3) & 1) * 8;
    const int achk = lane >> 4;
    const int wrow_min = q0 + 32 * w;     // warp owns rows wrow_min .. +31
    const int wrow_max = wrow_min + 31;

    for (int kvt = 0; kvt < ntiles; kvt++) {
        const int s = kvt & 1;
        if (kvt + 1 < ntiles) {
            load_kv(kvt + 1, s ^ 1);
            asm volatile("cp.async.commit_group;" ::: "memory");
            asm volatile("cp.async.wait_group 1;" ::: "memory");
        } else {
            asm volatile("cp.async.wait_group 0;" ::: "memory");
        }
        __syncthreads();
        if (kvt == 0) {
            #pragma unroll
            for (int mt = 0; mt < 2; mt++)
                #pragma unroll
                for (int ks = 0; ks < 4; ks++) {
                    uint32_t ad = sb + (uint32_t)((32 * w + 16 * mt + arow) * AT_ROWB +
                                                  (2 * ks + achk) * 16);
                    ldsm4(qhf[mt][ks], ad);
                    ldsm4(qlf[mt][ks], ad + AT_QTILE);
                }
        }
        const int c_base = kvt << 6;
        if (c_base <= wrow_max) {
            const uint32_t kb = sb + AT_KV0 + (uint32_t)s * AT_STG;

            // ---- S = Q K^T ----
            float sacc[2][8][4] = {};
            #pragma unroll
            for (int j = 0; j < 8; j++) {
                #pragma unroll
                for (int cp = 0; cp < 2; cp++) {
                    uint32_t khf[4], klf[4];
                    uint32_t ad = kb + (uint32_t)((8 * j + (lane & 7)) * AT_ROWB +
                                                  (4 * cp + (lane >> 3)) * 16);
                    ldsm4(khf, ad);
                    ldsm4(klf, ad + AT_KTILE);
                    #pragma unroll
                    for (int mt = 0; mt < 2; mt++) {
                        mma16816(sacc[mt][j], qhf[mt][2 * cp], &khf[0]);
                        mma16816(sacc[mt][j], qhf[mt][2 * cp], &klf[0]);
                        mma16816(sacc[mt][j], qlf[mt][2 * cp], &khf[0]);
                        mma16816(sacc[mt][j], qhf[mt][2 * cp + 1], &khf[2]);
                        mma16816(sacc[mt][j], qhf[mt][2 * cp + 1], &klf[2]);
                        mma16816(sacc[mt][j], qlf[mt][2 * cp + 1], &khf[2]);
                    }
                }
            }

            // ---- causal mask ----
            if (c_base + 63 > wrow_min) {
                #pragma unroll
                for (int mt = 0; mt < 2; mt++) {
                    const int lr0 = wrow_min + 16 * mt + g;
                    #pragma unroll
                    for (int j = 0; j < 8; j++) {
                        const int c0 = c_base + 8 * j + 2 * t;
                        if (c0     > lr0)     sacc[mt][j][0] = -1e30f;
                        if (c0 + 1 > lr0)     sacc[mt][j][1] = -1e30f;
                        if (c0     > lr0 + 8) sacc[mt][j][2] = -1e30f;
                        if (c0 + 1 > lr0 + 8) sacc[mt][j][3] = -1e30f;
                    }
                }
            }

            // ---- online softmax (base-2) per mt ----
            #pragma unroll
            for (int mt = 0; mt < 2; mt++) {
                float mx0 = -1e30f, mx1 = -1e30f;
                #pragma unroll
                for (int j = 0; j < 8; j++) {
                    mx0 = fmaxf(mx0, fmaxf(sacc[mt][j][0], sacc[mt][j][1]));
                    mx1 = fmaxf(mx1, fmaxf(sacc[mt][j][2], sacc[mt][j][3]));
                }
                mx0 = fmaxf(mx0, __shfl_xor_sync(0xffffffffu, mx0, 1));
                mx0 = fmaxf(mx0, __shfl_xor_sync(0xffffffffu, mx0, 2));
                mx1 = fmaxf(mx1, __shfl_xor_sync(0xffffffffu, mx1, 1));
                mx1 = fmaxf(mx1, __shfl_xor_sync(0xffffffffu, mx1, 2));
                const float mn0 = fmaxf(mrow[mt][0], mx0), mn1 = fmaxf(mrow[mt][1], mx1);
                const float al0 = exp2f(mrow[mt][0] - mn0), al1 = exp2f(mrow[mt][1] - mn1);
                float sum0 = 0.f, sum1 = 0.f;
                #pragma unroll
                for (int j = 0; j < 8; j++) {
                    sacc[mt][j][0] = exp2f(sacc[mt][j][0] - mn0);
                    sacc[mt][j][1] = exp2f(sacc[mt][j][1] - mn0);
                    sacc[mt][j][2] = exp2f(sacc[mt][j][2] - mn1);
                    sacc[mt][j][3] = exp2f(sacc[mt][j][3] - mn1);
                    sum0 += sacc[mt][j][0] + sacc[mt][j][1];
                    sum1 += sacc[mt][j][2] + sacc[mt][j][3];
                }
                sum0 += __shfl_xor_sync(0xffffffffu, sum0, 1);
                sum0 += __shfl_xor_sync(0xffffffffu, sum0, 2);
                sum1 += __shfl_xor_sync(0xffffffffu, sum1, 1);
                sum1 += __shfl_xor_sync(0xffffffffu, sum1, 2);
                lrow[mt][0] = lrow[mt][0] * al0 + sum0; mrow[mt][0] = mn0;
                lrow[mt][1] = lrow[mt][1] * al1 + sum1; mrow[mt][1] = mn1;
                #pragma unroll
                for (int j = 0; j < 8; j++) {
                    oacc[mt][j][0] *= al0; oacc[mt][j][1] *= al0;
                    oacc[mt][j][2] *= al1; oacc[mt][j][3] *= al1;
                }
            }

            // ---- O += P V: per-s2 P conversion (caps live registers) ----
            #pragma unroll
            for (int s2 = 0; s2 < 4; s2++) {
                uint32_t pah[2][4], pal[2][4];
                #pragma unroll
                for (int mt = 0; mt < 2; mt++) {
                    split2(sacc[mt][2 * s2][0],     sacc[mt][2 * s2][1],     pah[mt][0], pal[mt][0]);
                    split2(sacc[mt][2 * s2][2],     sacc[mt][2 * s2][3],     pah[mt][1], pal[mt][1]);
                    split2(sacc[mt][2 * s2 + 1][0], sacc[mt][2 * s2 + 1][1], pah[mt][2], pal[mt][2]);
                    split2(sacc[mt][2 * s2 + 1][2], sacc[mt][2 * s2 + 1][3], pah[mt][3], pal[mt][3]);
                }
                #pragma unroll
                for (int jp = 0; jp < 4; jp++) {
                    uint32_t vhf[4], vlf[4];
                    uint32_t ad = kb + 2 * AT_KTILE +
                        (uint32_t)((16 * s2 + (lane & 15)) * AT_ROWB + (2 * jp + (lane >> 4)) * 16);
                    ldsm4t(vhf, ad);
                    ldsm4t(vlf, ad + AT_KTILE);
                    #pragma unroll
                    for (int mt = 0; mt < 2; mt++) {
                        mma16816(oacc[mt][2 * jp],     pah[mt], &vhf[0]);
                        mma16816(oacc[mt][2 * jp],     pah[mt], &vlf[0]);
                        mma16816(oacc[mt][2 * jp],     pal[mt], &vhf[0]);
                        mma16816(oacc[mt][2 * jp + 1], pah[mt], &vhf[2]);
                        mma16816(oacc[mt][2 * jp + 1], pah[mt], &vlf[2]);
                        mma16816(oacc[mt][2 * jp + 1], pal[mt], &vhf[2]);
                    }
                }
            }
        }
        __syncthreads();
    }

    const int b = bh >> 4, h = bh & 15;
    #pragma unroll
    for (int mt = 0; mt < 2; mt++) {
        const float i0 = 1.f / lrow[mt][0], i1 = 1.f / lrow[mt][1];
        const size_t r0 = (size_t)b * P_SZ + q0 + 32 * w + 16 * mt + g;
        #pragma unroll
        for (int j = 0; j < 8; j++) {
            const int zc = h * 64 + 8 * j + 2 * t;
            uint32_t hu, lu;
            split2(oacc[mt][j][0] * i0, oacc[mt][j][1] * i0, hu, lu);
            *(uint32_t*)(zh + r0 * K_SZ + zc) = hu;
            *(uint32_t*)(zl + r0 * K_SZ + zc) = lu;
            split2(oacc[mt][j][2] * i1, oacc[mt][j][3] * i1, hu, lu);
            *(uint32_t*)(zh + (r0 + 8) * K_SZ + zc) = hu;
            *(uint32_t*)(zl + (r0 + 8) * K_SZ + zc) = lu;
        }
    }
}

// ---------------------------------------------------------------------------
extern "C" void kernel_launch(void* const* d_in, const int* in_sizes, int n_in,
                              void* d_out, int out_size)
{
    (void)in_sizes; (void)n_in; (void)out_size;
    const float* x      = (const float*)d_in[0];
    const float* W_attn = (const float*)d_in[1];
    const float* b_attn = (const float*)d_in[2];
    const float* W_proj = (const float*)d_in[3];
    const float* b_proj = (const float*)d_in[4];
    float* out = (float*)d_out;

    __nv_bfloat16 *xhi, *xlo, *wah, *wal, *wph, *wpl;
    __nv_bfloat16 *qh, *ql, *kh, *kl, *vh, *vl, *zh, *zl;
    cudaGetSymbolAddress((void**)&xhi, g_xhi);
    cudaGetSymbolAddress((void**)&xlo, g_xlo);
    cudaGetSymbolAddress((void**)&wah, g_wah);
    cudaGetSymbolAddress((void**)&wal, g_wal);
    cudaGetSymbolAddress((void**)&wph, g_wph);
    cudaGetSymbolAddress((void**)&wpl, g_wpl);
    cudaGetSymbolAddress((void**)&qh,  g_qh);
    cudaGetSymbolAddress((void**)&ql,  g_ql);
    cudaGetSymbolAddress((void**)&kh,  g_kh);
    cudaGetSymbolAddress((void**)&kl,  g_kl);
    cudaGetSymbolAddress((void**)&vh,  g_vh);
    cudaGetSymbolAddress((void**)&vl,  g_vl);
    cudaGetSymbolAddress((void**)&zh,  g_zh);
    cudaGetSymbolAddress((void**)&zl,  g_zl);

    cudaFuncSetAttribute(gemm_mma_kernel<0>,
                         cudaFuncAttributeMaxDynamicSharedMemorySize, GT_SMEM);
    cudaFuncSetAttribute(gemm_mma_kernel<1>,
                         cudaFuncAttributeMaxDynamicSharedMemorySize, GT_SMEM);
    cudaFuncSetAttribute(attn_mma_kernel,
                         cudaFuncAttributeMaxDynamicSharedMemorySize, AT_SMEM);

    split_kernel<<<(R_SZ * K_SZ / 4 + 255) / 256, 256>>>(x, xhi, xlo, R_SZ * K_SZ / 4);
    tsplit_kernel<<<dim3(N3_SZ / 32, K_SZ / 32), 256>>>(W_attn, wah, wal, K_SZ, N3_SZ);
    tsplit_kernel<<<dim3(M_SZ / 32, K_SZ / 32), 256>>>(W_proj, wph, wpl, K_SZ, M_SZ);

    gemm_mma_kernel<1><<<dim3(N3_SZ / 128, R_SZ / 128), 128, GT_SMEM>>>(
        xhi, xlo, wah, wal, b_attn, nullptr, N3_SZ, qh, ql, kh, kl, vh, vl);

    attn_mma_kernel<<<dim3(P_SZ / 128, BH_SZ), 128, AT_SMEM>>>(
        qh, ql, kh, kl, vh, vl, zh, zl);

    gemm_mma_kernel<0><<<dim3(M_SZ / 128, R_SZ / 128), 128, GT_SMEM>>>(
        zh, zl, wph, wpl, b_proj, out, M_SZ,
        nullptr, nullptr, nullptr, nullptr, nullptr, nullptr);
}